// round 12
// baseline (speedup 1.0000x reference)
#include <cuda_runtime.h>
#include <cuda_bf16.h>
#include <mma.h>
#include <cstdint>

using namespace nvcuda;

// Problem constants
#define BATCH   4
#define SQ      4096
#define SK      1024
#define D_EMB   1024
#define D_CRUZ  768
#define N_HEADS 16
#define D_HEAD  64

// Scratch (static device allocations — allowed)
__device__ float g_q[BATCH * SQ * D_EMB];     // 64 MB
__device__ float g_k[BATCH * SK * D_EMB];     // 16 MB
__device__ float g_v[BATCH * SK * D_EMB];     // 16 MB
__device__ float g_attn[BATCH * SQ * D_EMB];  // 64 MB
// tf32-pre-rounded inputs/weights
__device__ float g_xr[BATCH * SQ * D_EMB];    // 64 MB
__device__ float g_yr[BATCH * SK * D_CRUZ];   // 12 MB
__device__ float g_wq[D_EMB * D_EMB];         // 4 MB
__device__ float g_wk[D_CRUZ * D_EMB];        // 3 MB
__device__ float g_wv[D_CRUZ * D_EMB];        // 3 MB
__device__ float g_wo[D_EMB * D_EMB];         // 4 MB

// ---------------------------------------------------------------------------
// helpers
// ---------------------------------------------------------------------------
__device__ __forceinline__ void cp_async16(float* dst_smem, const float* src) {
    unsigned int d = (unsigned int)__cvta_generic_to_shared(dst_smem);
    asm volatile("cp.async.ca.shared.global [%0], [%1], 16;\n" :: "r"(d), "l"(src));
}
__device__ __forceinline__ void cp_commit() {
    asm volatile("cp.async.commit_group;\n");
}
template <int N>
__device__ __forceinline__ void cp_wait() {
    asm volatile("cp.async.wait_group %0;\n" :: "n"(N));
}

__device__ __forceinline__ uint32_t f2tf(float f) {
    uint32_t u;
    asm("cvt.rna.tf32.f32 %0, %1;" : "=r"(u) : "f"(f));
    return u;
}
__device__ __forceinline__ float roundtf(float f) {
    return __uint_as_float(f2tf(f));
}

// mma.m16n8k8 tf32 (verified layouts; gid=lane>>2, tig=lane&3):
//   A: a0=(gid,tig) a1=(gid+8,tig) a2=(gid,tig+4) a3=(gid+8,tig+4)
//   B: b0=(k=tig,n=gid) b1=(k=tig+4,n=gid)
//   C: c0=(gid,2tig) c1=(gid,2tig+1) c2=(gid+8,2tig) c3=(gid+8,2tig+1)
__device__ __forceinline__ void mma_tf32(float* d, const uint32_t* a,
                                         uint32_t b0, uint32_t b1) {
    asm volatile(
        "mma.sync.aligned.m16n8k8.row.col.f32.tf32.tf32.f32 "
        "{%0,%1,%2,%3}, {%4,%5,%6,%7}, {%8,%9}, {%0,%1,%2,%3};"
        : "+f"(d[0]), "+f"(d[1]), "+f"(d[2]), "+f"(d[3])
        : "r"(a[0]), "r"(a[1]), "r"(a[2]), "r"(a[3]), "r"(b0), "r"(b1));
}

// ---------------------------------------------------------------------------
// Pre-round: convert x, y, and the four weight matrices to tf32-rounded fp32.
// ---------------------------------------------------------------------------
#define SEG_X  4194304
#define SEG_Y  (SEG_X + 786432)
#define SEG_WQ (SEG_Y + 262144)
#define SEG_WK (SEG_WQ + 196608)
#define SEG_WV (SEG_WK + 196608)
#define SEG_WO (SEG_WV + 262144)

__global__ __launch_bounds__(256)
void preround_all(const float4* __restrict__ x, const float4* __restrict__ y,
                  const float4* __restrict__ wq, const float4* __restrict__ wk,
                  const float4* __restrict__ wv, const float4* __restrict__ wo,
                  float4* __restrict__ xr, float4* __restrict__ yr,
                  float4* __restrict__ wqr, float4* __restrict__ wkr,
                  float4* __restrict__ wvr, float4* __restrict__ wor) {
    for (long i = (long)blockIdx.x * blockDim.x + threadIdx.x; i < SEG_WO;
         i += (long)gridDim.x * blockDim.x) {
        const float4* src; float4* dst; long o;
        if (i < SEG_X)       { src = x;  dst = xr;  o = i; }
        else if (i < SEG_Y)  { src = y;  dst = yr;  o = i - SEG_X; }
        else if (i < SEG_WQ) { src = wq; dst = wqr; o = i - SEG_Y; }
        else if (i < SEG_WK) { src = wk; dst = wkr; o = i - SEG_WQ; }
        else if (i < SEG_WV) { src = wv; dst = wvr; o = i - SEG_WK; }
        else                 { src = wo; dst = wor; o = i - SEG_WV; }
        float4 v = src[o];
        v.x = roundtf(v.x); v.y = roundtf(v.y);
        v.z = roundtf(v.z); v.w = roundtf(v.w);
        dst[o] = v;
    }
}

// ---------------------------------------------------------------------------
// GEMM v4: 128x128x32 tf32, 3-stage cp.async ring, ONE barrier per k-tile.
// Safety argument: barrier at top of iter kt happens after all warps finish
// compute(kt-1) (they must pass cp_wait+barrier to proceed), so buffer
// (kt+2)%3 — last read at iter kt-1 — is free to overwrite post-barrier.
// Group discipline: exactly one commit per tile, group g == tile g.
// cp_wait<1> at iter kt ensures groups <= kt complete; last iter uses wait<0>.
// ---------------------------------------------------------------------------
#define BM 128
#define BN 128
#define BK 32
#define LDA 40
#define LDB 136
#define A_STG (BM * LDA)
#define B_STG (BK * LDB)
#define STG_FLOATS (A_STG + B_STG)              // 9472
#define GSTAGES 3
#define GEMM_SMEM_BYTES (GSTAGES * STG_FLOATS * 4)  // 113664

template <bool ROUND_OUT>
__global__ __launch_bounds__(256, 2)
void gemm_bias_tf32_v4(const float* __restrict__ A, const float* __restrict__ W,
                       const float* __restrict__ bias, float* __restrict__ C,
                       int M, int N, int K) {
    extern __shared__ float sm[];
    const int tid  = threadIdx.x;
    const int warp = tid >> 5;
    const int wm   = warp >> 1;
    const int wn   = warp & 1;
    const int bm   = blockIdx.y * BM;
    const int bn   = blockIdx.x * BN;

    wmma::fragment<wmma::accumulator, 16, 16, 8, float> acc[2][4];
#pragma unroll
    for (int r = 0; r < 2; r++)
#pragma unroll
        for (int c = 0; c < 4; c++) wmma::fill_fragment(acc[r][c], 0.0f);

    auto issue = [&](int kt, int buf) {
        float* As = sm + buf * STG_FLOATS;
        float* Bs = As + A_STG;
        const float* Ag = A + (size_t)bm * K + kt * BK;
        const float* Wg = W + (size_t)(kt * BK) * N + bn;
#pragma unroll
        for (int i = 0; i < 4; i++) {
            int p   = tid + i * 256;
            int row = p >> 3;
            int col = (p & 7) * 4;
            cp_async16(&As[row * LDA + col], Ag + (size_t)row * K + col);
        }
#pragma unroll
        for (int i = 0; i < 4; i++) {
            int p   = tid + i * 256;
            int row = p >> 5;
            int col = (p & 31) * 4;
            cp_async16(&Bs[row * LDB + col], Wg + (size_t)row * N + col);
        }
    };

    const int NK = K / BK;                      // 32 or 24 (>= 3)
    issue(0, 0); cp_commit();
    issue(1, 1); cp_commit();

    for (int kt = 0; kt < NK; kt++) {
        if (kt == NK - 1) cp_wait<0>(); else cp_wait<1>();
        __syncthreads();                        // buffer kt%3 ready; compute(kt-1) done in all warps

        if (kt + 2 < NK) {                      // overwrite buffer (kt+2)%3 — safe post-barrier
            issue(kt + 2, (kt + 2) % GSTAGES);
            cp_commit();
        }

        float* As = sm + (kt % GSTAGES) * STG_FLOATS;
        float* Bs = As + A_STG;
#pragma unroll
        for (int kk = 0; kk < BK; kk += 8) {
            wmma::fragment<wmma::matrix_a, 16, 16, 8, wmma::precision::tf32, wmma::row_major> a[2];
#pragma unroll
            for (int r = 0; r < 2; r++)
                wmma::load_matrix_sync(a[r], &As[(wm * 32 + r * 16) * LDA + kk], LDA);
#pragma unroll
            for (int c = 0; c < 4; c++) {
                wmma::fragment<wmma::matrix_b, 16, 16, 8, wmma::precision::tf32, wmma::row_major> b;
                wmma::load_matrix_sync(b, &Bs[kk * LDB + wn * 64 + c * 16], LDB);
#pragma unroll
                for (int r = 0; r < 2; r++)
                    wmma::mma_sync(acc[r][c], a[r], b, acc[r][c]);
            }
        }
        // no trailing barrier — 3-stage ring makes it redundant
    }

    __syncthreads();                            // Cs overlaps stage buffers
    float* Cs = sm;
#pragma unroll
    for (int r = 0; r < 2; r++)
#pragma unroll
        for (int c = 0; c < 4; c++)
            wmma::store_matrix_sync(&Cs[(wm * 32 + r * 16) * LDB + wn * 64 + c * 16],
                                    acc[r][c], LDB, wmma::mem_row_major);
    __syncthreads();

#pragma unroll
    for (int i = 0; i < 16; i++) {
        int p   = tid + i * 256;
        int row = p >> 5;
        int col = (p & 31) * 4;
        float4 v = *reinterpret_cast<float4*>(&Cs[row * LDB + col]);
        float4 bb = *reinterpret_cast<const float4*>(&bias[bn + col]);
        v.x += bb.x; v.y += bb.y; v.z += bb.z; v.w += bb.w;
        if (ROUND_OUT) {
            v.x = roundtf(v.x); v.y = roundtf(v.y);
            v.z = roundtf(v.z); v.w = roundtf(v.w);
        }
        *reinterpret_cast<float4*>(&C[(size_t)(bm + row) * N + bn + col]) = v;
    }
}

// ---------------------------------------------------------------------------
// Flash attention v8 (unchanged from round 11): register-resident FA2,
// 110.6 KB smem, 2 CTAs/SM.
// ---------------------------------------------------------------------------
#define QT 128
#define KT 64
#define LDQ 68
#define LDK 76
#define LDV 72
#define QS_FL (QT * LDQ)
#define KS_FL (KT * LDK)
#define VS_FL (KT * LDV)
#define ATTN_SMEM_FLOATS (QS_FL + 2 * KS_FL + 2 * VS_FL)
#define ATTN_SMEM_BYTES  (ATTN_SMEM_FLOATS * 4) // 110592 B

__global__ __launch_bounds__(256, 2)
void attn_fa2_tf32(const float* __restrict__ qg, const float* __restrict__ kg,
                   const float* __restrict__ vg, float* __restrict__ og) {
    extern __shared__ float smem[];
    float* Qs = smem;                           // 128 x 68
    float* Kb = Qs + QS_FL;                     // 2 x 64 x 76
    float* Vb = Kb + 2 * KS_FL;                 // 2 x 64 x 72

    const int tid  = threadIdx.x;
    const int warp = tid >> 5;
    const int lane = tid & 31;
    const int gid  = lane >> 2;
    const int tig  = lane & 3;
    const int q0 = blockIdx.x * QT;
    const int h  = blockIdx.y;
    const int b  = blockIdx.z;
    const float scale = 0.125f;

#pragma unroll
    for (int i = 0; i < 8; i++) {
        int p   = tid + i * 256;
        int row = p >> 4;
        int col = (p & 15) * 4;
        float4 v = *reinterpret_cast<const float4*>(
            &qg[((size_t)(b * SQ + q0 + row)) * D_EMB + h * D_HEAD + col]);
        v.x *= scale; v.y *= scale; v.z *= scale; v.w *= scale;
        *reinterpret_cast<float4*>(&Qs[row * LDQ + col]) = v;
    }
    __syncthreads();

    const int r0 = warp * 16 + gid;
    uint32_t qf[8][4];
#pragma unroll
    for (int kc = 0; kc < 8; kc++) {
        qf[kc][0] = __float_as_uint(Qs[r0 * LDQ + kc * 8 + tig]);
        qf[kc][1] = __float_as_uint(Qs[(r0 + 8) * LDQ + kc * 8 + tig]);
        qf[kc][2] = __float_as_uint(Qs[r0 * LDQ + kc * 8 + tig + 4]);
        qf[kc][3] = __float_as_uint(Qs[(r0 + 8) * LDQ + kc * 8 + tig + 4]);
    }

    float o[8][4];
#pragma unroll
    for (int j = 0; j < 8; j++)
#pragma unroll
        for (int e = 0; e < 4; e++) o[j][e] = 0.0f;
    float m0 = -1e30f, m1 = -1e30f, l0 = 0.0f, l1 = 0.0f;

    auto issue_kv = [&](int kt, int buf) {
        const int k0 = kt * KT;
        float* Ks = Kb + buf * KS_FL;
        float* Vs = Vb + buf * VS_FL;
#pragma unroll
        for (int i = 0; i < 4; i++) {
            int p   = tid + i * 256;
            int row = p >> 4;
            int col = (p & 15) * 4;
            size_t g = ((size_t)(b * SK + k0 + row)) * D_EMB + h * D_HEAD + col;
            cp_async16(&Ks[row * LDK + col], &kg[g]);
            cp_async16(&Vs[row * LDV + col], &vg[g]);
        }
    };

    issue_kv(0, 0);
    cp_commit();

    const int NKT = SK / KT;
    for (int kt = 0; kt < NKT; kt++) {
        if (kt + 1 < NKT) {
            issue_kv(kt + 1, (kt + 1) & 1);
            cp_commit();
            cp_wait<1>();
        } else {
            cp_wait<0>();
        }
        __syncthreads();

        const float* Ks = Kb + (kt & 1) * KS_FL;
        const float* Vs = Vb + (kt & 1) * VS_FL;

        float s[8][4];
#pragma unroll
        for (int j = 0; j < 8; j++)
#pragma unroll
            for (int e = 0; e < 4; e++) s[j][e] = 0.0f;

#pragma unroll
        for (int kc = 0; kc < 8; kc++) {
#pragma unroll
            for (int j = 0; j < 8; j++) {
                uint32_t b0 = __float_as_uint(Ks[(j * 8 + gid) * LDK + kc * 8 + tig]);
                uint32_t b1 = __float_as_uint(Ks[(j * 8 + gid) * LDK + kc * 8 + tig + 4]);
                mma_tf32(s[j], qf[kc], b0, b1);
            }
        }

        float mx0 = -1e30f, mx1 = -1e30f;
#pragma unroll
        for (int j = 0; j < 8; j++) {
            mx0 = fmaxf(mx0, fmaxf(s[j][0], s[j][1]));
            mx1 = fmaxf(mx1, fmaxf(s[j][2], s[j][3]));
        }
        mx0 = fmaxf(mx0, __shfl_xor_sync(0xffffffffu, mx0, 1));
        mx0 = fmaxf(mx0, __shfl_xor_sync(0xffffffffu, mx0, 2));
        mx1 = fmaxf(mx1, __shfl_xor_sync(0xffffffffu, mx1, 1));
        mx1 = fmaxf(mx1, __shfl_xor_sync(0xffffffffu, mx1, 2));

        const float mn0 = fmaxf(m0, mx0);
        const float mn1 = fmaxf(m1, mx1);
        float sum0 = 0.0f, sum1 = 0.0f;
#pragma unroll
        for (int j = 0; j < 8; j++) {
            s[j][0] = __expf(s[j][0] - mn0);
            s[j][1] = __expf(s[j][1] - mn0);
            s[j][2] = __expf(s[j][2] - mn1);
            s[j][3] = __expf(s[j][3] - mn1);
            sum0 += s[j][0] + s[j][1];
            sum1 += s[j][2] + s[j][3];
        }
        sum0 += __shfl_xor_sync(0xffffffffu, sum0, 1);
        sum0 += __shfl_xor_sync(0xffffffffu, sum0, 2);
        sum1 += __shfl_xor_sync(0xffffffffu, sum1, 1);
        sum1 += __shfl_xor_sync(0xffffffffu, sum1, 2);

        const float al0 = __expf(m0 - mn0);
        const float al1 = __expf(m1 - mn1);
        l0 = l0 * al0 + sum0;
        l1 = l1 * al1 + sum1;
        m0 = mn0; m1 = mn1;

#pragma unroll
        for (int j = 0; j < 8; j++) {
            o[j][0] *= al0; o[j][1] *= al0;
            o[j][2] *= al1; o[j][3] *= al1;
        }

        uint32_t pa[8][4];
        const int srcA = (lane & ~3) | (tig >> 1);
        const int srcB = (lane & ~3) | (2 + (tig >> 1));
        const bool oddc = (tig & 1);
#pragma unroll
        for (int j = 0; j < 8; j++) {
            float x0 = __shfl_sync(0xffffffffu, s[j][0], srcA);
            float x1 = __shfl_sync(0xffffffffu, s[j][1], srcA);
            float y0 = __shfl_sync(0xffffffffu, s[j][0], srcB);
            float y1 = __shfl_sync(0xffffffffu, s[j][1], srcB);
            float z0 = __shfl_sync(0xffffffffu, s[j][2], srcA);
            float z1 = __shfl_sync(0xffffffffu, s[j][3], srcA);
            float w0 = __shfl_sync(0xffffffffu, s[j][2], srcB);
            float w1 = __shfl_sync(0xffffffffu, s[j][3], srcB);
            pa[j][0] = f2tf(oddc ? x1 : x0);
            pa[j][1] = f2tf(oddc ? z1 : z0);
            pa[j][2] = f2tf(oddc ? y1 : y0);
            pa[j][3] = f2tf(oddc ? w1 : w0);
        }

#pragma unroll
        for (int kc = 0; kc < 8; kc++) {
#pragma unroll
            for (int j = 0; j < 8; j++) {
                uint32_t b0 = __float_as_uint(Vs[(kc * 8 + tig) * LDV + j * 8 + gid]);
                uint32_t b1 = __float_as_uint(Vs[(kc * 8 + tig + 4) * LDV + j * 8 + gid]);
                mma_tf32(o[j], pa[kc], b0, b1);
            }
        }
        __syncthreads();
    }

    const float inv0 = 1.0f / l0;
    const float inv1 = 1.0f / l1;
    const size_t rowbase0 = ((size_t)(b * SQ + q0 + r0)) * D_EMB + h * D_HEAD;
    const size_t rowbase1 = rowbase0 + 8 * D_EMB;
#pragma unroll
    for (int j = 0; j < 8; j++) {
        int col = j * 8 + 2 * tig;
        *reinterpret_cast<float2*>(&og[rowbase0 + col]) =
            make_float2(roundtf(o[j][0] * inv0), roundtf(o[j][1] * inv0));
        *reinterpret_cast<float2*>(&og[rowbase1 + col]) =
            make_float2(roundtf(o[j][2] * inv1), roundtf(o[j][3] * inv1));
    }
}

// ---------------------------------------------------------------------------
// Launcher
// ---------------------------------------------------------------------------
extern "C" void kernel_launch(void* const* d_in, const int* in_sizes, int n_in,
                              void* d_out, int out_size) {
    const float* x  = (const float*)d_in[0];
    const float* y  = (const float*)d_in[1];
    const float* Wq = (const float*)d_in[2];
    const float* bq = (const float*)d_in[3];
    const float* Wk = (const float*)d_in[4];
    const float* bk = (const float*)d_in[5];
    const float* Wv = (const float*)d_in[6];
    const float* bv = (const float*)d_in[7];
    const float* Wo = (const float*)d_in[8];
    const float* bo = (const float*)d_in[9];
    float* out = (float*)d_out;

    float *gq, *gk, *gv, *ga, *xr, *yr, *wqr, *wkr, *wvr, *wor;
    cudaGetSymbolAddress((void**)&gq, g_q);
    cudaGetSymbolAddress((void**)&gk, g_k);
    cudaGetSymbolAddress((void**)&gv, g_v);
    cudaGetSymbolAddress((void**)&ga, g_attn);
    cudaGetSymbolAddress((void**)&xr, g_xr);
    cudaGetSymbolAddress((void**)&yr, g_yr);
    cudaGetSymbolAddress((void**)&wqr, g_wq);
    cudaGetSymbolAddress((void**)&wkr, g_wk);
    cudaGetSymbolAddress((void**)&wvr, g_wv);
    cudaGetSymbolAddress((void**)&wor, g_wo);

    cudaFuncSetAttribute(gemm_bias_tf32_v4<true>,
                         cudaFuncAttributeMaxDynamicSharedMemorySize, GEMM_SMEM_BYTES);
    cudaFuncSetAttribute(gemm_bias_tf32_v4<false>,
                         cudaFuncAttributeMaxDynamicSharedMemorySize, GEMM_SMEM_BYTES);
    cudaFuncSetAttribute(attn_fa2_tf32,
                         cudaFuncAttributeMaxDynamicSharedMemorySize, ATTN_SMEM_BYTES);

    // Pre-round inputs + weights to tf32
    preround_all<<<2048, 256>>>((const float4*)x, (const float4*)y,
                                (const float4*)Wq, (const float4*)Wk,
                                (const float4*)Wv, (const float4*)Wo,
                                (float4*)xr, (float4*)yr, (float4*)wqr,
                                (float4*)wkr, (float4*)wvr, (float4*)wor);

    // Projections (outputs tf32-rounded)
    gemm_bias_tf32_v4<true><<<dim3(D_EMB / BN, (BATCH * SQ) / BM), 256, GEMM_SMEM_BYTES>>>(
        xr, wqr, bq, gq, BATCH * SQ, D_EMB, D_EMB);
    gemm_bias_tf32_v4<true><<<dim3(D_EMB / BN, (BATCH * SK) / BM), 256, GEMM_SMEM_BYTES>>>(
        yr, wkr, bk, gk, BATCH * SK, D_EMB, D_CRUZ);
    gemm_bias_tf32_v4<true><<<dim3(D_EMB / BN, (BATCH * SK) / BM), 256, GEMM_SMEM_BYTES>>>(
        yr, wvr, bv, gv, BATCH * SK, D_EMB, D_CRUZ);

    // Attention (register-resident FA2)
    attn_fa2_tf32<<<dim3(SQ / QT, N_HEADS, BATCH), 256, ATTN_SMEM_BYTES>>>(gq, gk, gv, ga);

    // Output projection (full-precision fp32 output)
    gemm_bias_tf32_v4<false><<<dim3(D_EMB / BN, (BATCH * SQ) / BM), 256, GEMM_SMEM_BYTES>>>(
        ga, wor, bo, out, BATCH * SQ, D_EMB, D_EMB);
}

// round 13
// speedup vs baseline: 1.0607x; 1.0607x over previous
#include <cuda_runtime.h>
#include <cuda_bf16.h>
#include <mma.h>
#include <cstdint>

using namespace nvcuda;

// Problem constants
#define BATCH   4
#define SQ      4096
#define SK      1024
#define D_EMB   1024
#define D_CRUZ  768
#define N_HEADS 16
#define D_HEAD  64

// Scratch (static device allocations — allowed)
__device__ float g_q[BATCH * SQ * D_EMB];     // 64 MB
__device__ float g_k[BATCH * SK * D_EMB];     // 16 MB
__device__ float g_v[BATCH * SK * D_EMB];     // 16 MB
__device__ float g_attn[BATCH * SQ * D_EMB];  // 64 MB
// tf32-pre-rounded inputs/weights
__device__ float g_xr[BATCH * SQ * D_EMB];    // 64 MB
__device__ float g_yr[BATCH * SK * D_CRUZ];   // 12 MB
__device__ float g_wq[D_EMB * D_EMB];         // 4 MB
__device__ float g_wk[D_CRUZ * D_EMB];        // 3 MB
__device__ float g_wv[D_CRUZ * D_EMB];        // 3 MB
__device__ float g_wo[D_EMB * D_EMB];         // 4 MB

// ---------------------------------------------------------------------------
// helpers
// ---------------------------------------------------------------------------
__device__ __forceinline__ void cp_async16(float* dst_smem, const float* src) {
    unsigned int d = (unsigned int)__cvta_generic_to_shared(dst_smem);
    asm volatile("cp.async.ca.shared.global [%0], [%1], 16;\n" :: "r"(d), "l"(src));
}
__device__ __forceinline__ void cp_commit() {
    asm volatile("cp.async.commit_group;\n");
}
template <int N>
__device__ __forceinline__ void cp_wait() {
    asm volatile("cp.async.wait_group %0;\n" :: "n"(N));
}

__device__ __forceinline__ uint32_t f2tf(float f) {
    uint32_t u;
    asm("cvt.rna.tf32.f32 %0, %1;" : "=r"(u) : "f"(f));
    return u;
}
__device__ __forceinline__ float roundtf(float f) {
    return __uint_as_float(f2tf(f));
}

// mma.m16n8k8 tf32 (verified layouts; gid=lane>>2, tig=lane&3):
//   A: a0=(gid,tig) a1=(gid+8,tig) a2=(gid,tig+4) a3=(gid+8,tig+4)
//   B: b0=(k=tig,n=gid) b1=(k=tig+4,n=gid)
//   C: c0=(gid,2tig) c1=(gid,2tig+1) c2=(gid+8,2tig) c3=(gid+8,2tig+1)
__device__ __forceinline__ void mma_tf32(float* d, const uint32_t* a,
                                         uint32_t b0, uint32_t b1) {
    asm volatile(
        "mma.sync.aligned.m16n8k8.row.col.f32.tf32.tf32.f32 "
        "{%0,%1,%2,%3}, {%4,%5,%6,%7}, {%8,%9}, {%0,%1,%2,%3};"
        : "+f"(d[0]), "+f"(d[1]), "+f"(d[2]), "+f"(d[3])
        : "r"(a[0]), "r"(a[1]), "r"(a[2]), "r"(a[3]), "r"(b0), "r"(b1));
}

// ---------------------------------------------------------------------------
// Pre-round: convert x, y, and the four weight matrices to tf32-rounded fp32.
// ---------------------------------------------------------------------------
#define SEG_X  4194304
#define SEG_Y  (SEG_X + 786432)
#define SEG_WQ (SEG_Y + 262144)
#define SEG_WK (SEG_WQ + 196608)
#define SEG_WV (SEG_WK + 196608)
#define SEG_WO (SEG_WV + 262144)

__global__ __launch_bounds__(256)
void preround_all(const float4* __restrict__ x, const float4* __restrict__ y,
                  const float4* __restrict__ wq, const float4* __restrict__ wk,
                  const float4* __restrict__ wv, const float4* __restrict__ wo,
                  float4* __restrict__ xr, float4* __restrict__ yr,
                  float4* __restrict__ wqr, float4* __restrict__ wkr,
                  float4* __restrict__ wvr, float4* __restrict__ wor) {
    for (long i = (long)blockIdx.x * blockDim.x + threadIdx.x; i < SEG_WO;
         i += (long)gridDim.x * blockDim.x) {
        const float4* src; float4* dst; long o;
        if (i < SEG_X)       { src = x;  dst = xr;  o = i; }
        else if (i < SEG_Y)  { src = y;  dst = yr;  o = i - SEG_X; }
        else if (i < SEG_WQ) { src = wq; dst = wqr; o = i - SEG_Y; }
        else if (i < SEG_WK) { src = wk; dst = wkr; o = i - SEG_WQ; }
        else if (i < SEG_WV) { src = wv; dst = wvr; o = i - SEG_WK; }
        else                 { src = wo; dst = wor; o = i - SEG_WV; }
        float4 v = src[o];
        v.x = roundtf(v.x); v.y = roundtf(v.y);
        v.z = roundtf(v.z); v.w = roundtf(v.w);
        dst[o] = v;
    }
}

// ---------------------------------------------------------------------------
// GEMM v5: v3's proven 2-stage cp.async structure + explicit fragment
// double-buffering over the kk loop (load kk+8's fragments into independent
// registers before issuing kk's MMAs). No min-blocks reg clamp: ILP > occ.
// ---------------------------------------------------------------------------
#define BM 128
#define BN 128
#define BK 32
#define LDA 40
#define LDB 136
#define A_STG (BM * LDA)
#define B_STG (BK * LDB)
#define STG_FLOATS (A_STG + B_STG)
#define GEMM_SMEM_BYTES (2 * STG_FLOATS * 4)    // 75776

template <bool ROUND_OUT>
__global__ __launch_bounds__(256)
void gemm_bias_tf32_v5(const float* __restrict__ A, const float* __restrict__ W,
                       const float* __restrict__ bias, float* __restrict__ C,
                       int M, int N, int K) {
    extern __shared__ float sm[];
    const int tid  = threadIdx.x;
    const int warp = tid >> 5;
    const int wm   = warp >> 1;
    const int wn   = warp & 1;
    const int bm   = blockIdx.y * BM;
    const int bn   = blockIdx.x * BN;

    wmma::fragment<wmma::accumulator, 16, 16, 8, float> acc[2][4];
#pragma unroll
    for (int r = 0; r < 2; r++)
#pragma unroll
        for (int c = 0; c < 4; c++) wmma::fill_fragment(acc[r][c], 0.0f);

    auto issue = [&](int kt, int buf) {
        float* As = sm + buf * STG_FLOATS;
        float* Bs = As + A_STG;
        const float* Ag = A + (size_t)bm * K + kt * BK;
        const float* Wg = W + (size_t)(kt * BK) * N + bn;
#pragma unroll
        for (int i = 0; i < 4; i++) {
            int p   = tid + i * 256;
            int row = p >> 3;
            int col = (p & 7) * 4;
            cp_async16(&As[row * LDA + col], Ag + (size_t)row * K + col);
        }
#pragma unroll
        for (int i = 0; i < 4; i++) {
            int p   = tid + i * 256;
            int row = p >> 5;
            int col = (p & 31) * 4;
            cp_async16(&Bs[row * LDB + col], Wg + (size_t)row * N + col);
        }
    };

    // Fragment double buffers (independent regs -> ptxas can overlap LDS w/ MMA)
    wmma::fragment<wmma::matrix_a, 16, 16, 8, wmma::precision::tf32, wmma::row_major> af[2][2];
    wmma::fragment<wmma::matrix_b, 16, 16, 8, wmma::precision::tf32, wmma::row_major> bf[2][4];

    const int NK = K / BK;
    issue(0, 0);
    cp_commit();

    for (int kt = 0; kt < NK; kt++) {
        if (kt + 1 < NK) {
            issue(kt + 1, (kt + 1) & 1);
            cp_commit();
            cp_wait<1>();
        } else {
            cp_wait<0>();
        }
        __syncthreads();

        float* As = sm + (kt & 1) * STG_FLOATS;
        float* Bs = As + A_STG;

        // preload kk=0 fragments
#pragma unroll
        for (int r = 0; r < 2; r++)
            wmma::load_matrix_sync(af[0][r], &As[(wm * 32 + r * 16) * LDA + 0], LDA);
#pragma unroll
        for (int c = 0; c < 4; c++)
            wmma::load_matrix_sync(bf[0][c], &Bs[0 * LDB + wn * 64 + c * 16], LDB);

#pragma unroll
        for (int kki = 0; kki < 4; kki++) {     // kk = kki*8
            const int cur = kki & 1;
            const int nxt = cur ^ 1;
            if (kki < 3) {
                const int kk2 = (kki + 1) * 8;
#pragma unroll
                for (int r = 0; r < 2; r++)
                    wmma::load_matrix_sync(af[nxt][r], &As[(wm * 32 + r * 16) * LDA + kk2], LDA);
#pragma unroll
                for (int c = 0; c < 4; c++)
                    wmma::load_matrix_sync(bf[nxt][c], &Bs[kk2 * LDB + wn * 64 + c * 16], LDB);
            }
#pragma unroll
            for (int c = 0; c < 4; c++)
#pragma unroll
                for (int r = 0; r < 2; r++)
                    wmma::mma_sync(acc[r][c], af[cur][r], bf[cur][c], acc[r][c]);
        }
        __syncthreads();
    }

    float* Cs = sm;
#pragma unroll
    for (int r = 0; r < 2; r++)
#pragma unroll
        for (int c = 0; c < 4; c++)
            wmma::store_matrix_sync(&Cs[(wm * 32 + r * 16) * LDB + wn * 64 + c * 16],
                                    acc[r][c], LDB, wmma::mem_row_major);
    __syncthreads();

#pragma unroll
    for (int i = 0; i < 16; i++) {
        int p   = tid + i * 256;
        int row = p >> 5;
        int col = (p & 31) * 4;
        float4 v = *reinterpret_cast<float4*>(&Cs[row * LDB + col]);
        float4 bb = *reinterpret_cast<const float4*>(&bias[bn + col]);
        v.x += bb.x; v.y += bb.y; v.z += bb.z; v.w += bb.w;
        if (ROUND_OUT) {
            v.x = roundtf(v.x); v.y = roundtf(v.y);
            v.z = roundtf(v.z); v.w = roundtf(v.w);
        }
        *reinterpret_cast<float4*>(&C[(size_t)(bm + row) * N + bn + col]) = v;
    }
}

// ---------------------------------------------------------------------------
// Flash attention v8 (round-11 version, unchanged): register-resident FA2,
// 110.6 KB smem, 2 CTAs/SM.
// ---------------------------------------------------------------------------
#define QT 128
#define KT 64
#define LDQ 68
#define LDK 76
#define LDV 72
#define QS_FL (QT * LDQ)
#define KS_FL (KT * LDK)
#define VS_FL (KT * LDV)
#define ATTN_SMEM_FLOATS (QS_FL + 2 * KS_FL + 2 * VS_FL)
#define ATTN_SMEM_BYTES  (ATTN_SMEM_FLOATS * 4) // 110592 B

__global__ __launch_bounds__(256, 2)
void attn_fa2_tf32(const float* __restrict__ qg, const float* __restrict__ kg,
                   const float* __restrict__ vg, float* __restrict__ og) {
    extern __shared__ float smem[];
    float* Qs = smem;
    float* Kb = Qs + QS_FL;
    float* Vb = Kb + 2 * KS_FL;

    const int tid  = threadIdx.x;
    const int warp = tid >> 5;
    const int lane = tid & 31;
    const int gid  = lane >> 2;
    const int tig  = lane & 3;
    const int q0 = blockIdx.x * QT;
    const int h  = blockIdx.y;
    const int b  = blockIdx.z;
    const float scale = 0.125f;

#pragma unroll
    for (int i = 0; i < 8; i++) {
        int p   = tid + i * 256;
        int row = p >> 4;
        int col = (p & 15) * 4;
        float4 v = *reinterpret_cast<const float4*>(
            &qg[((size_t)(b * SQ + q0 + row)) * D_EMB + h * D_HEAD + col]);
        v.x *= scale; v.y *= scale; v.z *= scale; v.w *= scale;
        *reinterpret_cast<float4*>(&Qs[row * LDQ + col]) = v;
    }
    __syncthreads();

    const int r0 = warp * 16 + gid;
    uint32_t qf[8][4];
#pragma unroll
    for (int kc = 0; kc < 8; kc++) {
        qf[kc][0] = __float_as_uint(Qs[r0 * LDQ + kc * 8 + tig]);
        qf[kc][1] = __float_as_uint(Qs[(r0 + 8) * LDQ + kc * 8 + tig]);
        qf[kc][2] = __float_as_uint(Qs[r0 * LDQ + kc * 8 + tig + 4]);
        qf[kc][3] = __float_as_uint(Qs[(r0 + 8) * LDQ + kc * 8 + tig + 4]);
    }

    float o[8][4];
#pragma unroll
    for (int j = 0; j < 8; j++)
#pragma unroll
        for (int e = 0; e < 4; e++) o[j][e] = 0.0f;
    float m0 = -1e30f, m1 = -1e30f, l0 = 0.0f, l1 = 0.0f;

    auto issue_kv = [&](int kt, int buf) {
        const int k0 = kt * KT;
        float* Ks = Kb + buf * KS_FL;
        float* Vs = Vb + buf * VS_FL;
#pragma unroll
        for (int i = 0; i < 4; i++) {
            int p   = tid + i * 256;
            int row = p >> 4;
            int col = (p & 15) * 4;
            size_t g = ((size_t)(b * SK + k0 + row)) * D_EMB + h * D_HEAD + col;
            cp_async16(&Ks[row * LDK + col], &kg[g]);
            cp_async16(&Vs[row * LDV + col], &vg[g]);
        }
    };

    issue_kv(0, 0);
    cp_commit();

    const int NKT = SK / KT;
    for (int kt = 0; kt < NKT; kt++) {
        if (kt + 1 < NKT) {
            issue_kv(kt + 1, (kt + 1) & 1);
            cp_commit();
            cp_wait<1>();
        } else {
            cp_wait<0>();
        }
        __syncthreads();

        const float* Ks = Kb + (kt & 1) * KS_FL;
        const float* Vs = Vb + (kt & 1) * VS_FL;

        float s[8][4];
#pragma unroll
        for (int j = 0; j < 8; j++)
#pragma unroll
            for (int e = 0; e < 4; e++) s[j][e] = 0.0f;

#pragma unroll
        for (int kc = 0; kc < 8; kc++) {
#pragma unroll
            for (int j = 0; j < 8; j++) {
                uint32_t b0 = __float_as_uint(Ks[(j * 8 + gid) * LDK + kc * 8 + tig]);
                uint32_t b1 = __float_as_uint(Ks[(j * 8 + gid) * LDK + kc * 8 + tig + 4]);
                mma_tf32(s[j], qf[kc], b0, b1);
            }
        }

        float mx0 = -1e30f, mx1 = -1e30f;
#pragma unroll
        for (int j = 0; j < 8; j++) {
            mx0 = fmaxf(mx0, fmaxf(s[j][0], s[j][1]));
            mx1 = fmaxf(mx1, fmaxf(s[j][2], s[j][3]));
        }
        mx0 = fmaxf(mx0, __shfl_xor_sync(0xffffffffu, mx0, 1));
        mx0 = fmaxf(mx0, __shfl_xor_sync(0xffffffffu, mx0, 2));
        mx1 = fmaxf(mx1, __shfl_xor_sync(0xffffffffu, mx1, 1));
        mx1 = fmaxf(mx1, __shfl_xor_sync(0xffffffffu, mx1, 2));

        const float mn0 = fmaxf(m0, mx0);
        const float mn1 = fmaxf(m1, mx1);
        float sum0 = 0.0f, sum1 = 0.0f;
#pragma unroll
        for (int j = 0; j < 8; j++) {
            s[j][0] = __expf(s[j][0] - mn0);
            s[j][1] = __expf(s[j][1] - mn0);
            s[j][2] = __expf(s[j][2] - mn1);
            s[j][3] = __expf(s[j][3] - mn1);
            sum0 += s[j][0] + s[j][1];
            sum1 += s[j][2] + s[j][3];
        }
        sum0 += __shfl_xor_sync(0xffffffffu, sum0, 1);
        sum0 += __shfl_xor_sync(0xffffffffu, sum0, 2);
        sum1 += __shfl_xor_sync(0xffffffffu, sum1, 1);
        sum1 += __shfl_xor_sync(0xffffffffu, sum1, 2);

        const float al0 = __expf(m0 - mn0);
        const float al1 = __expf(m1 - mn1);
        l0 = l0 * al0 + sum0;
        l1 = l1 * al1 + sum1;
        m0 = mn0; m1 = mn1;

#pragma unroll
        for (int j = 0; j < 8; j++) {
            o[j][0] *= al0; o[j][1] *= al0;
            o[j][2] *= al1; o[j][3] *= al1;
        }

        uint32_t pa[8][4];
        const int srcA = (lane & ~3) | (tig >> 1);
        const int srcB = (lane & ~3) | (2 + (tig >> 1));
        const bool oddc = (tig & 1);
#pragma unroll
        for (int j = 0; j < 8; j++) {
            float x0 = __shfl_sync(0xffffffffu, s[j][0], srcA);
            float x1 = __shfl_sync(0xffffffffu, s[j][1], srcA);
            float y0 = __shfl_sync(0xffffffffu, s[j][0], srcB);
            float y1 = __shfl_sync(0xffffffffu, s[j][1], srcB);
            float z0 = __shfl_sync(0xffffffffu, s[j][2], srcA);
            float z1 = __shfl_sync(0xffffffffu, s[j][3], srcA);
            float w0 = __shfl_sync(0xffffffffu, s[j][2], srcB);
            float w1 = __shfl_sync(0xffffffffu, s[j][3], srcB);
            pa[j][0] = f2tf(oddc ? x1 : x0);
            pa[j][1] = f2tf(oddc ? z1 : z0);
            pa[j][2] = f2tf(oddc ? y1 : y0);
            pa[j][3] = f2tf(oddc ? w1 : w0);
        }

#pragma unroll
        for (int kc = 0; kc < 8; kc++) {
#pragma unroll
            for (int j = 0; j < 8; j++) {
                uint32_t b0 = __float_as_uint(Vs[(kc * 8 + tig) * LDV + j * 8 + gid]);
                uint32_t b1 = __float_as_uint(Vs[(kc * 8 + tig + 4) * LDV + j * 8 + gid]);
                mma_tf32(o[j], pa[kc], b0, b1);
            }
        }
        __syncthreads();
    }

    const float inv0 = 1.0f / l0;
    const float inv1 = 1.0f / l1;
    const size_t rowbase0 = ((size_t)(b * SQ + q0 + r0)) * D_EMB + h * D_HEAD;
    const size_t rowbase1 = rowbase0 + 8 * D_EMB;
#pragma unroll
    for (int j = 0; j < 8; j++) {
        int col = j * 8 + 2 * tig;
        *reinterpret_cast<float2*>(&og[rowbase0 + col]) =
            make_float2(roundtf(o[j][0] * inv0), roundtf(o[j][1] * inv0));
        *reinterpret_cast<float2*>(&og[rowbase1 + col]) =
            make_float2(roundtf(o[j][2] * inv1), roundtf(o[j][3] * inv1));
    }
}

// ---------------------------------------------------------------------------
// Launcher
// ---------------------------------------------------------------------------
extern "C" void kernel_launch(void* const* d_in, const int* in_sizes, int n_in,
                              void* d_out, int out_size) {
    const float* x  = (const float*)d_in[0];
    const float* y  = (const float*)d_in[1];
    const float* Wq = (const float*)d_in[2];
    const float* bq = (const float*)d_in[3];
    const float* Wk = (const float*)d_in[4];
    const float* bk = (const float*)d_in[5];
    const float* Wv = (const float*)d_in[6];
    const float* bv = (const float*)d_in[7];
    const float* Wo = (const float*)d_in[8];
    const float* bo = (const float*)d_in[9];
    float* out = (float*)d_out;

    float *gq, *gk, *gv, *ga, *xr, *yr, *wqr, *wkr, *wvr, *wor;
    cudaGetSymbolAddress((void**)&gq, g_q);
    cudaGetSymbolAddress((void**)&gk, g_k);
    cudaGetSymbolAddress((void**)&gv, g_v);
    cudaGetSymbolAddress((void**)&ga, g_attn);
    cudaGetSymbolAddress((void**)&xr, g_xr);
    cudaGetSymbolAddress((void**)&yr, g_yr);
    cudaGetSymbolAddress((void**)&wqr, g_wq);
    cudaGetSymbolAddress((void**)&wkr, g_wk);
    cudaGetSymbolAddress((void**)&wvr, g_wv);
    cudaGetSymbolAddress((void**)&wor, g_wo);

    cudaFuncSetAttribute(gemm_bias_tf32_v5<true>,
                         cudaFuncAttributeMaxDynamicSharedMemorySize, GEMM_SMEM_BYTES);
    cudaFuncSetAttribute(gemm_bias_tf32_v5<false>,
                         cudaFuncAttributeMaxDynamicSharedMemorySize, GEMM_SMEM_BYTES);
    cudaFuncSetAttribute(attn_fa2_tf32,
                         cudaFuncAttributeMaxDynamicSharedMemorySize, ATTN_SMEM_BYTES);

    // Pre-round inputs + weights to tf32
    preround_all<<<2048, 256>>>((const float4*)x, (const float4*)y,
                                (const float4*)Wq, (const float4*)Wk,
                                (const float4*)Wv, (const float4*)Wo,
                                (float4*)xr, (float4*)yr, (float4*)wqr,
                                (float4*)wkr, (float4*)wvr, (float4*)wor);

    // Projections (outputs tf32-rounded)
    gemm_bias_tf32_v5<true><<<dim3(D_EMB / BN, (BATCH * SQ) / BM), 256, GEMM_SMEM_BYTES>>>(
        xr, wqr, bq, gq, BATCH * SQ, D_EMB, D_EMB);
    gemm_bias_tf32_v5<true><<<dim3(D_EMB / BN, (BATCH * SK) / BM), 256, GEMM_SMEM_BYTES>>>(
        yr, wkr, bk, gk, BATCH * SK, D_EMB, D_CRUZ);
    gemm_bias_tf32_v5<true><<<dim3(D_EMB / BN, (BATCH * SK) / BM), 256, GEMM_SMEM_BYTES>>>(
        yr, wvr, bv, gv, BATCH * SK, D_EMB, D_CRUZ);

    // Attention (register-resident FA2)
    attn_fa2_tf32<<<dim3(SQ / QT, N_HEADS, BATCH), 256, ATTN_SMEM_BYTES>>>(gq, gk, gv, ga);

    // Output projection (full-precision fp32 output)
    gemm_bias_tf32_v5<false><<<dim3(D_EMB / BN, (BATCH * SQ) / BM), 256, GEMM_SMEM_BYTES>>>(
        ga, wor, bo, out, BATCH * SQ, D_EMB, D_EMB);
}

// round 14
// speedup vs baseline: 1.6500x; 1.5555x over previous
#include <cuda_runtime.h>
#include <cuda_bf16.h>
#include <mma.h>
#include <cstdint>

// Problem constants
#define BATCH   4
#define SQ      4096
#define SK      1024
#define D_EMB   1024
#define D_CRUZ  768
#define N_HEADS 16
#define D_HEAD  64

// Scratch (static device allocations — allowed)
__device__ float g_q[BATCH * SQ * D_EMB];     // 64 MB
__device__ float g_k[BATCH * SK * D_EMB];     // 16 MB
__device__ float g_v[BATCH * SK * D_EMB];     // 16 MB
__device__ float g_attn[BATCH * SQ * D_EMB];  // 64 MB
// tf32-pre-rounded inputs/weights
__device__ float g_xr[BATCH * SQ * D_EMB];    // 64 MB
__device__ float g_yr[BATCH * SK * D_CRUZ];   // 12 MB
__device__ float g_wq[D_EMB * D_EMB];         // 4 MB
__device__ float g_wk[D_CRUZ * D_EMB];        // 3 MB
__device__ float g_wv[D_CRUZ * D_EMB];        // 3 MB
__device__ float g_wo[D_EMB * D_EMB];         // 4 MB

// ---------------------------------------------------------------------------
// helpers
// ---------------------------------------------------------------------------
__device__ __forceinline__ void cp_async16(float* dst_smem, const float* src) {
    unsigned int d = (unsigned int)__cvta_generic_to_shared(dst_smem);
    asm volatile("cp.async.ca.shared.global [%0], [%1], 16;\n" :: "r"(d), "l"(src));
}
__device__ __forceinline__ void cp_commit() {
    asm volatile("cp.async.commit_group;\n");
}
template <int N>
__device__ __forceinline__ void cp_wait() {
    asm volatile("cp.async.wait_group %0;\n" :: "n"(N));
}

__device__ __forceinline__ uint32_t f2tf(float f) {
    uint32_t u;
    asm("cvt.rna.tf32.f32 %0, %1;" : "=r"(u) : "f"(f));
    return u;
}
__device__ __forceinline__ float roundtf(float f) {
    return __uint_as_float(f2tf(f));
}

// mma.m16n8k8 tf32 (verified layouts; gid=lane>>2, tig=lane&3):
//   A: a0=(gid,tig) a1=(gid+8,tig) a2=(gid,tig+4) a3=(gid+8,tig+4)
//   B: b0=(k=tig,n=gid) b1=(k=tig+4,n=gid)
//   C: c0=(gid,2tig) c1=(gid,2tig+1) c2=(gid+8,2tig) c3=(gid+8,2tig+1)
__device__ __forceinline__ void mma_tf32(float* d, const uint32_t* a,
                                         uint32_t b0, uint32_t b1) {
    asm volatile(
        "mma.sync.aligned.m16n8k8.row.col.f32.tf32.tf32.f32 "
        "{%0,%1,%2,%3}, {%4,%5,%6,%7}, {%8,%9}, {%0,%1,%2,%3};"
        : "+f"(d[0]), "+f"(d[1]), "+f"(d[2]), "+f"(d[3])
        : "r"(a[0]), "r"(a[1]), "r"(a[2]), "r"(a[3]), "r"(b0), "r"(b1));
}

// ---------------------------------------------------------------------------
// Pre-round: convert x, y, and the four weight matrices to tf32-rounded fp32.
// ---------------------------------------------------------------------------
#define SEG_X  4194304
#define SEG_Y  (SEG_X + 786432)
#define SEG_WQ (SEG_Y + 262144)
#define SEG_WK (SEG_WQ + 196608)
#define SEG_WV (SEG_WK + 196608)
#define SEG_WO (SEG_WV + 262144)

__global__ __launch_bounds__(256)
void preround_all(const float4* __restrict__ x, const float4* __restrict__ y,
                  const float4* __restrict__ wq, const float4* __restrict__ wk,
                  const float4* __restrict__ wv, const float4* __restrict__ wo,
                  float4* __restrict__ xr, float4* __restrict__ yr,
                  float4* __restrict__ wqr, float4* __restrict__ wkr,
                  float4* __restrict__ wvr, float4* __restrict__ wor) {
    for (long i = (long)blockIdx.x * blockDim.x + threadIdx.x; i < SEG_WO;
         i += (long)gridDim.x * blockDim.x) {
        const float4* src; float4* dst; long o;
        if (i < SEG_X)       { src = x;  dst = xr;  o = i; }
        else if (i < SEG_Y)  { src = y;  dst = yr;  o = i - SEG_X; }
        else if (i < SEG_WQ) { src = wq; dst = wqr; o = i - SEG_Y; }
        else if (i < SEG_WK) { src = wk; dst = wkr; o = i - SEG_WQ; }
        else if (i < SEG_WV) { src = wv; dst = wvr; o = i - SEG_WK; }
        else                 { src = wo; dst = wor; o = i - SEG_WV; }
        float4 v = src[o];
        v.x = roundtf(v.x); v.y = roundtf(v.y);
        v.z = roundtf(v.z); v.w = roundtf(v.w);
        dst[o] = v;
    }
}

// ---------------------------------------------------------------------------
// GEMM v6: raw mma.sync, conflict-free smem strides, register fragment
// double-buffering, direct register->gmem epilogue. 128x128x32 tiles,
// 8 warps (4x2), warp tile 32x64 = 2(m) x 8(n) m16n8k8 tiles.
// Bank audit (one instruction = 32 lanes):
//   A frag: addr=(...+gid)*36 + tig  -> bank (4*gid+tig)%32: 32 distinct ✓
//   B frag: addr=(...+tig)*136 + gid -> bank (8*tig+gid)%32: 32 distinct ✓
// Pipeline: v3's proven 2-stage prefetch-before-wait.
// ---------------------------------------------------------------------------
#define BM 128
#define BN 128
#define BK 32
#define LDA 36
#define LDB 136
#define A_STG (BM * LDA)                        // 4608
#define B_STG (BK * LDB)                        // 4352
#define STG_FLOATS (A_STG + B_STG)              // 8960
#define GEMM_SMEM_BYTES (2 * STG_FLOATS * 4)    // 71680

template <bool ROUND_OUT>
__global__ __launch_bounds__(256)
void gemm_bias_tf32_v6(const float* __restrict__ A, const float* __restrict__ W,
                       const float* __restrict__ bias, float* __restrict__ C,
                       int M, int N, int K) {
    extern __shared__ float sm[];
    const int tid  = threadIdx.x;
    const int warp = tid >> 5;
    const int lane = tid & 31;
    const int gid  = lane >> 2;
    const int tig  = lane & 3;
    const int wm   = warp >> 1;                 // 0..3 -> 32-row band
    const int wn   = warp & 1;                  // 0..1 -> 64-col band
    const int bm   = blockIdx.y * BM;
    const int bn   = blockIdx.x * BN;

    float acc[2][8][4];                         // [mt][nt][c-regs]
#pragma unroll
    for (int mt = 0; mt < 2; mt++)
#pragma unroll
        for (int nt = 0; nt < 8; nt++)
#pragma unroll
            for (int e = 0; e < 4; e++) acc[mt][nt][e] = 0.0f;

    auto issue = [&](int kt, int buf) {
        float* As = sm + buf * STG_FLOATS;
        float* Bs = As + A_STG;
        const float* Ag = A + (size_t)bm * K + kt * BK;
        const float* Wg = W + (size_t)(kt * BK) * N + bn;
#pragma unroll
        for (int i = 0; i < 4; i++) {           // A: 128x32 = 1024 float4
            int p   = tid + i * 256;
            int row = p >> 3;
            int col = (p & 7) * 4;
            cp_async16(&As[row * LDA + col], Ag + (size_t)row * K + col);
        }
#pragma unroll
        for (int i = 0; i < 4; i++) {           // B: 32x128 = 1024 float4
            int p   = tid + i * 256;
            int row = p >> 5;
            int col = (p & 31) * 4;
            cp_async16(&Bs[row * LDB + col], Wg + (size_t)row * N + col);
        }
    };

    const int NK = K / BK;
    issue(0, 0);
    cp_commit();

    for (int kt = 0; kt < NK; kt++) {
        if (kt + 1 < NK) {
            issue(kt + 1, (kt + 1) & 1);
            cp_commit();
            cp_wait<1>();
        } else {
            cp_wait<0>();
        }
        __syncthreads();

        const float* As = sm + (kt & 1) * STG_FLOATS;
        const float* Bs = As + A_STG;
        const int ar0 = (wm * 32 + gid) * LDA;          // row gid of m-tile 0
        const int ar1 = ar0 + 8 * LDA;                  // row gid+8
        const int ar2 = ar0 + 16 * LDA;                 // m-tile 1
        const int ar3 = ar0 + 24 * LDA;
        const int bc  = wn * 64 + gid;

        uint32_t af[2][2][4];                   // [buf][mt][4]
        uint32_t bfr[2][8][2];                  // [buf][nt][2]

        // preload kk=0 fragments
#pragma unroll
        for (int mt = 0; mt < 2; mt++) {
            const int rA = (mt == 0) ? ar0 : ar2;
            const int rB = (mt == 0) ? ar1 : ar3;
            af[0][mt][0] = __float_as_uint(As[rA + tig]);
            af[0][mt][1] = __float_as_uint(As[rB + tig]);
            af[0][mt][2] = __float_as_uint(As[rA + tig + 4]);
            af[0][mt][3] = __float_as_uint(As[rB + tig + 4]);
        }
#pragma unroll
        for (int nt = 0; nt < 8; nt++) {
            bfr[0][nt][0] = __float_as_uint(Bs[tig * LDB + bc + nt * 8]);
            bfr[0][nt][1] = __float_as_uint(Bs[(tig + 4) * LDB + bc + nt * 8]);
        }

#pragma unroll
        for (int kki = 0; kki < 4; kki++) {     // kk = kki*8
            const int cur = kki & 1;
            const int nxt = cur ^ 1;
            if (kki < 3) {
                const int kk2 = (kki + 1) * 8;
#pragma unroll
                for (int mt = 0; mt < 2; mt++) {
                    const int rA = ((mt == 0) ? ar0 : ar2) + kk2;
                    const int rB = ((mt == 0) ? ar1 : ar3) + kk2;
                    af[nxt][mt][0] = __float_as_uint(As[rA + tig]);
                    af[nxt][mt][1] = __float_as_uint(As[rB + tig]);
                    af[nxt][mt][2] = __float_as_uint(As[rA + tig + 4]);
                    af[nxt][mt][3] = __float_as_uint(As[rB + tig + 4]);
                }
#pragma unroll
                for (int nt = 0; nt < 8; nt++) {
                    bfr[nxt][nt][0] = __float_as_uint(Bs[(kk2 + tig) * LDB + bc + nt * 8]);
                    bfr[nxt][nt][1] = __float_as_uint(Bs[(kk2 + tig + 4) * LDB + bc + nt * 8]);
                }
            }
#pragma unroll
            for (int nt = 0; nt < 8; nt++)
#pragma unroll
                for (int mt = 0; mt < 2; mt++)
                    mma_tf32(acc[mt][nt], af[cur][mt], bfr[cur][nt][0], bfr[cur][nt][1]);
        }
        __syncthreads();                        // all reads done before next issue overwrites
    }

    // Direct epilogue: C layout c0=(gid,2tig) c1=(gid,2tig+1) c2/c3=row+8
#pragma unroll
    for (int mt = 0; mt < 2; mt++) {
        const int row0 = bm + wm * 32 + mt * 16 + gid;
#pragma unroll
        for (int nt = 0; nt < 8; nt++) {
            const int col = bn + wn * 64 + nt * 8 + 2 * tig;
            const float b0 = bias[col];
            const float b1 = bias[col + 1];
            float v0 = acc[mt][nt][0] + b0, v1 = acc[mt][nt][1] + b1;
            float v2 = acc[mt][nt][2] + b0, v3 = acc[mt][nt][3] + b1;
            if (ROUND_OUT) {
                v0 = roundtf(v0); v1 = roundtf(v1);
                v2 = roundtf(v2); v3 = roundtf(v3);
            }
            *reinterpret_cast<float2*>(&C[(size_t)row0 * N + col]) = make_float2(v0, v1);
            *reinterpret_cast<float2*>(&C[(size_t)(row0 + 8) * N + col]) = make_float2(v2, v3);
        }
    }
}

// ---------------------------------------------------------------------------
// Flash attention v8 (round-11 version, unchanged): register-resident FA2,
// 110.6 KB smem, 2 CTAs/SM.
// ---------------------------------------------------------------------------
#define QT 128
#define KT 64
#define LDQ 68
#define LDK 76
#define LDV 72
#define QS_FL (QT * LDQ)
#define KS_FL (KT * LDK)
#define VS_FL (KT * LDV)
#define ATTN_SMEM_FLOATS (QS_FL + 2 * KS_FL + 2 * VS_FL)
#define ATTN_SMEM_BYTES  (ATTN_SMEM_FLOATS * 4) // 110592 B

__global__ __launch_bounds__(256, 2)
void attn_fa2_tf32(const float* __restrict__ qg, const float* __restrict__ kg,
                   const float* __restrict__ vg, float* __restrict__ og) {
    extern __shared__ float smem[];
    float* Qs = smem;
    float* Kb = Qs + QS_FL;
    float* Vb = Kb + 2 * KS_FL;

    const int tid  = threadIdx.x;
    const int warp = tid >> 5;
    const int lane = tid & 31;
    const int gid  = lane >> 2;
    const int tig  = lane & 3;
    const int q0 = blockIdx.x * QT;
    const int h  = blockIdx.y;
    const int b  = blockIdx.z;
    const float scale = 0.125f;

#pragma unroll
    for (int i = 0; i < 8; i++) {
        int p   = tid + i * 256;
        int row = p >> 4;
        int col = (p & 15) * 4;
        float4 v = *reinterpret_cast<const float4*>(
            &qg[((size_t)(b * SQ + q0 + row)) * D_EMB + h * D_HEAD + col]);
        v.x *= scale; v.y *= scale; v.z *= scale; v.w *= scale;
        *reinterpret_cast<float4*>(&Qs[row * LDQ + col]) = v;
    }
    __syncthreads();

    const int r0 = warp * 16 + gid;
    uint32_t qf[8][4];
#pragma unroll
    for (int kc = 0; kc < 8; kc++) {
        qf[kc][0] = __float_as_uint(Qs[r0 * LDQ + kc * 8 + tig]);
        qf[kc][1] = __float_as_uint(Qs[(r0 + 8) * LDQ + kc * 8 + tig]);
        qf[kc][2] = __float_as_uint(Qs[r0 * LDQ + kc * 8 + tig + 4]);
        qf[kc][3] = __float_as_uint(Qs[(r0 + 8) * LDQ + kc * 8 + tig + 4]);
    }

    float o[8][4];
#pragma unroll
    for (int j = 0; j < 8; j++)
#pragma unroll
        for (int e = 0; e < 4; e++) o[j][e] = 0.0f;
    float m0 = -1e30f, m1 = -1e30f, l0 = 0.0f, l1 = 0.0f;

    auto issue_kv = [&](int kt, int buf) {
        const int k0 = kt * KT;
        float* Ks = Kb + buf * KS_FL;
        float* Vs = Vb + buf * VS_FL;
#pragma unroll
        for (int i = 0; i < 4; i++) {
            int p   = tid + i * 256;
            int row = p >> 4;
            int col = (p & 15) * 4;
            size_t g = ((size_t)(b * SK + k0 + row)) * D_EMB + h * D_HEAD + col;
            cp_async16(&Ks[row * LDK + col], &kg[g]);
            cp_async16(&Vs[row * LDV + col], &vg[g]);
        }
    };

    issue_kv(0, 0);
    cp_commit();

    const int NKT = SK / KT;
    for (int kt = 0; kt < NKT; kt++) {
        if (kt + 1 < NKT) {
            issue_kv(kt + 1, (kt + 1) & 1);
            cp_commit();
            cp_wait<1>();
        } else {
            cp_wait<0>();
        }
        __syncthreads();

        const float* Ks = Kb + (kt & 1) * KS_FL;
        const float* Vs = Vb + (kt & 1) * VS_FL;

        float s[8][4];
#pragma unroll
        for (int j = 0; j < 8; j++)
#pragma unroll
            for (int e = 0; e < 4; e++) s[j][e] = 0.0f;

#pragma unroll
        for (int kc = 0; kc < 8; kc++) {
#pragma unroll
            for (int j = 0; j < 8; j++) {
                uint32_t b0 = __float_as_uint(Ks[(j * 8 + gid) * LDK + kc * 8 + tig]);
                uint32_t b1 = __float_as_uint(Ks[(j * 8 + gid) * LDK + kc * 8 + tig + 4]);
                mma_tf32(s[j], qf[kc], b0, b1);
            }
        }

        float mx0 = -1e30f, mx1 = -1e30f;
#pragma unroll
        for (int j = 0; j < 8; j++) {
            mx0 = fmaxf(mx0, fmaxf(s[j][0], s[j][1]));
            mx1 = fmaxf(mx1, fmaxf(s[j][2], s[j][3]));
        }
        mx0 = fmaxf(mx0, __shfl_xor_sync(0xffffffffu, mx0, 1));
        mx0 = fmaxf(mx0, __shfl_xor_sync(0xffffffffu, mx0, 2));
        mx1 = fmaxf(mx1, __shfl_xor_sync(0xffffffffu, mx1, 1));
        mx1 = fmaxf(mx1, __shfl_xor_sync(0xffffffffu, mx1, 2));

        const float mn0 = fmaxf(m0, mx0);
        const float mn1 = fmaxf(m1, mx1);
        float sum0 = 0.0f, sum1 = 0.0f;
#pragma unroll
        for (int j = 0; j < 8; j++) {
            s[j][0] = __expf(s[j][0] - mn0);
            s[j][1] = __expf(s[j][1] - mn0);
            s[j][2] = __expf(s[j][2] - mn1);
            s[j][3] = __expf(s[j][3] - mn1);
            sum0 += s[j][0] + s[j][1];
            sum1 += s[j][2] + s[j][3];
        }
        sum0 += __shfl_xor_sync(0xffffffffu, sum0, 1);
        sum0 += __shfl_xor_sync(0xffffffffu, sum0, 2);
        sum1 += __shfl_xor_sync(0xffffffffu, sum1, 1);
        sum1 += __shfl_xor_sync(0xffffffffu, sum1, 2);

        const float al0 = __expf(m0 - mn0);
        const float al1 = __expf(m1 - mn1);
        l0 = l0 * al0 + sum0;
        l1 = l1 * al1 + sum1;
        m0 = mn0; m1 = mn1;

#pragma unroll
        for (int j = 0; j < 8; j++) {
            o[j][0] *= al0; o[j][1] *= al0;
            o[j][2] *= al1; o[j][3] *= al1;
        }

        uint32_t pa[8][4];
        const int srcA = (lane & ~3) | (tig >> 1);
        const int srcB = (lane & ~3) | (2 + (tig >> 1));
        const bool oddc = (tig & 1);
#pragma unroll
        for (int j = 0; j < 8; j++) {
            float x0 = __shfl_sync(0xffffffffu, s[j][0], srcA);
            float x1 = __shfl_sync(0xffffffffu, s[j][1], srcA);
            float y0 = __shfl_sync(0xffffffffu, s[j][0], srcB);
            float y1 = __shfl_sync(0xffffffffu, s[j][1], srcB);
            float z0 = __shfl_sync(0xffffffffu, s[j][2], srcA);
            float z1 = __shfl_sync(0xffffffffu, s[j][3], srcA);
            float w0 = __shfl_sync(0xffffffffu, s[j][2], srcB);
            float w1 = __shfl_sync(0xffffffffu, s[j][3], srcB);
            pa[j][0] = f2tf(oddc ? x1 : x0);
            pa[j][1] = f2tf(oddc ? z1 : z0);
            pa[j][2] = f2tf(oddc ? y1 : y0);
            pa[j][3] = f2tf(oddc ? w1 : w0);
        }

#pragma unroll
        for (int kc = 0; kc < 8; kc++) {
#pragma unroll
            for (int j = 0; j < 8; j++) {
                uint32_t b0 = __float_as_uint(Vs[(kc * 8 + tig) * LDV + j * 8 + gid]);
                uint32_t b1 = __float_as_uint(Vs[(kc * 8 + tig + 4) * LDV + j * 8 + gid]);
                mma_tf32(o[j], pa[kc], b0, b1);
            }
        }
        __syncthreads();
    }

    const float inv0 = 1.0f / l0;
    const float inv1 = 1.0f / l1;
    const size_t rowbase0 = ((size_t)(b * SQ + q0 + r0)) * D_EMB + h * D_HEAD;
    const size_t rowbase1 = rowbase0 + 8 * D_EMB;
#pragma unroll
    for (int j = 0; j < 8; j++) {
        int col = j * 8 + 2 * tig;
        *reinterpret_cast<float2*>(&og[rowbase0 + col]) =
            make_float2(roundtf(o[j][0] * inv0), roundtf(o[j][1] * inv0));
        *reinterpret_cast<float2*>(&og[rowbase1 + col]) =
            make_float2(roundtf(o[j][2] * inv1), roundtf(o[j][3] * inv1));
    }
}

// ---------------------------------------------------------------------------
// Launcher
// ---------------------------------------------------------------------------
extern "C" void kernel_launch(void* const* d_in, const int* in_sizes, int n_in,
                              void* d_out, int out_size) {
    const float* x  = (const float*)d_in[0];
    const float* y  = (const float*)d_in[1];
    const float* Wq = (const float*)d_in[2];
    const float* bq = (const float*)d_in[3];
    const float* Wk = (const float*)d_in[4];
    const float* bk = (const float*)d_in[5];
    const float* Wv = (const float*)d_in[6];
    const float* bv = (const float*)d_in[7];
    const float* Wo = (const float*)d_in[8];
    const float* bo = (const float*)d_in[9];
    float* out = (float*)d_out;

    float *gq, *gk, *gv, *ga, *xr, *yr, *wqr, *wkr, *wvr, *wor;
    cudaGetSymbolAddress((void**)&gq, g_q);
    cudaGetSymbolAddress((void**)&gk, g_k);
    cudaGetSymbolAddress((void**)&gv, g_v);
    cudaGetSymbolAddress((void**)&ga, g_attn);
    cudaGetSymbolAddress((void**)&xr, g_xr);
    cudaGetSymbolAddress((void**)&yr, g_yr);
    cudaGetSymbolAddress((void**)&wqr, g_wq);
    cudaGetSymbolAddress((void**)&wkr, g_wk);
    cudaGetSymbolAddress((void**)&wvr, g_wv);
    cudaGetSymbolAddress((void**)&wor, g_wo);

    cudaFuncSetAttribute(gemm_bias_tf32_v6<true>,
                         cudaFuncAttributeMaxDynamicSharedMemorySize, GEMM_SMEM_BYTES);
    cudaFuncSetAttribute(gemm_bias_tf32_v6<false>,
                         cudaFuncAttributeMaxDynamicSharedMemorySize, GEMM_SMEM_BYTES);
    cudaFuncSetAttribute(attn_fa2_tf32,
                         cudaFuncAttributeMaxDynamicSharedMemorySize, ATTN_SMEM_BYTES);

    // Pre-round inputs + weights to tf32
    preround_all<<<2048, 256>>>((const float4*)x, (const float4*)y,
                                (const float4*)Wq, (const float4*)Wk,
                                (const float4*)Wv, (const float4*)Wo,
                                (float4*)xr, (float4*)yr, (float4*)wqr,
                                (float4*)wkr, (float4*)wvr, (float4*)wor);

    // Projections (outputs tf32-rounded)
    gemm_bias_tf32_v6<true><<<dim3(D_EMB / BN, (BATCH * SQ) / BM), 256, GEMM_SMEM_BYTES>>>(
        xr, wqr, bq, gq, BATCH * SQ, D_EMB, D_EMB);
    gemm_bias_tf32_v6<true><<<dim3(D_EMB / BN, (BATCH * SK) / BM), 256, GEMM_SMEM_BYTES>>>(
        yr, wkr, bk, gk, BATCH * SK, D_EMB, D_CRUZ);
    gemm_bias_tf32_v6<true><<<dim3(D_EMB / BN, (BATCH * SK) / BM), 256, GEMM_SMEM_BYTES>>>(
        yr, wvr, bv, gv, BATCH * SK, D_EMB, D_CRUZ);

    // Attention (register-resident FA2)
    attn_fa2_tf32<<<dim3(SQ / QT, N_HEADS, BATCH), 256, ATTN_SMEM_BYTES>>>(gq, gk, gv, ga);

    // Output projection (full-precision fp32 output)
    gemm_bias_tf32_v6<false><<<dim3(D_EMB / BN, (BATCH * SQ) / BM), 256, GEMM_SMEM_BYTES>>>(
        ga, wor, bo, out, BATCH * SQ, D_EMB, D_EMB);
}

// round 16
// speedup vs baseline: 1.7000x; 1.0303x over previous
#include <cuda_runtime.h>
#include <cuda_bf16.h>
#include <mma.h>
#include <cstdint>

// Problem constants
#define BATCH   4
#define SQ      4096
#define SK      1024
#define D_EMB   1024
#define D_CRUZ  768
#define N_HEADS 16
#define D_HEAD  64

// Scratch (static device allocations — allowed)
__device__ float g_q[BATCH * SQ * D_EMB];     // 64 MB
__device__ float g_k[BATCH * SK * D_EMB];     // 16 MB
__device__ float g_v[BATCH * SK * D_EMB];     // 16 MB
__device__ float g_attn[BATCH * SQ * D_EMB];  // 64 MB
// tf32-pre-rounded inputs/weights
__device__ float g_xr[BATCH * SQ * D_EMB];    // 64 MB
__device__ float g_yr[BATCH * SK * D_CRUZ];   // 12 MB
__device__ float g_wq[D_EMB * D_EMB];         // 4 MB
__device__ float g_wk[D_CRUZ * D_EMB];        // 3 MB
__device__ float g_wv[D_CRUZ * D_EMB];        // 3 MB
__device__ float g_wo[D_EMB * D_EMB];         // 4 MB

// ---------------------------------------------------------------------------
// helpers
// ---------------------------------------------------------------------------
__device__ __forceinline__ void cp_async16(float* dst_smem, const float* src) {
    unsigned int d = (unsigned int)__cvta_generic_to_shared(dst_smem);
    asm volatile("cp.async.ca.shared.global [%0], [%1], 16;\n" :: "r"(d), "l"(src));
}
__device__ __forceinline__ void cp_commit() {
    asm volatile("cp.async.commit_group;\n");
}
template <int N>
__device__ __forceinline__ void cp_wait() {
    asm volatile("cp.async.wait_group %0;\n" :: "n"(N));
}

__device__ __forceinline__ uint32_t f2tf(float f) {
    uint32_t u;
    asm("cvt.rna.tf32.f32 %0, %1;" : "=r"(u) : "f"(f));
    return u;
}
__device__ __forceinline__ float roundtf(float f) {
    return __uint_as_float(f2tf(f));
}

// mma.m16n8k8 tf32 (verified layouts; gid=lane>>2, tig=lane&3):
//   A: a0=(gid,tig) a1=(gid+8,tig) a2=(gid,tig+4) a3=(gid+8,tig+4)
//   B: b0=(k=tig,n=gid) b1=(k=tig+4,n=gid)
//   C: c0=(gid,2tig) c1=(gid,2tig+1) c2=(gid+8,2tig) c3=(gid+8,2tig+1)
__device__ __forceinline__ void mma_tf32(float* d, const uint32_t* a,
                                         uint32_t b0, uint32_t b1) {
    asm volatile(
        "mma.sync.aligned.m16n8k8.row.col.f32.tf32.tf32.f32 "
        "{%0,%1,%2,%3}, {%4,%5,%6,%7}, {%8,%9}, {%0,%1,%2,%3};"
        : "+f"(d[0]), "+f"(d[1]), "+f"(d[2]), "+f"(d[3])
        : "r"(a[0]), "r"(a[1]), "r"(a[2]), "r"(a[3]), "r"(b0), "r"(b1));
}

// ---------------------------------------------------------------------------
// Pre-round: convert x, y, and the four weight matrices to tf32-rounded fp32.
// ---------------------------------------------------------------------------
#define SEG_X  4194304
#define SEG_Y  (SEG_X + 786432)
#define SEG_WQ (SEG_Y + 262144)
#define SEG_WK (SEG_WQ + 196608)
#define SEG_WV (SEG_WK + 196608)
#define SEG_WO (SEG_WV + 262144)

__global__ __launch_bounds__(256)
void preround_all(const float4* __restrict__ x, const float4* __restrict__ y,
                  const float4* __restrict__ wq, const float4* __restrict__ wk,
                  const float4* __restrict__ wv, const float4* __restrict__ wo,
                  float4* __restrict__ xr, float4* __restrict__ yr,
                  float4* __restrict__ wqr, float4* __restrict__ wkr,
                  float4* __restrict__ wvr, float4* __restrict__ wor) {
    for (long i = (long)blockIdx.x * blockDim.x + threadIdx.x; i < SEG_WO;
         i += (long)gridDim.x * blockDim.x) {
        const float4* src; float4* dst; long o;
        if (i < SEG_X)       { src = x;  dst = xr;  o = i; }
        else if (i < SEG_Y)  { src = y;  dst = yr;  o = i - SEG_X; }
        else if (i < SEG_WQ) { src = wq; dst = wqr; o = i - SEG_Y; }
        else if (i < SEG_WK) { src = wk; dst = wkr; o = i - SEG_WQ; }
        else if (i < SEG_WV) { src = wv; dst = wvr; o = i - SEG_WK; }
        else                 { src = wo; dst = wor; o = i - SEG_WV; }
        float4 v = src[o];
        v.x = roundtf(v.x); v.y = roundtf(v.y);
        v.z = roundtf(v.z); v.w = roundtf(v.w);
        dst[o] = v;
    }
}

// ---------------------------------------------------------------------------
// GEMM v7: raw mma.sync, 128x128x32 tiles, 4 warps (2x2), warp tile 64x64
// (4 m-tiles x 8 n-tiles = 32 MMAs per kk-step vs 32 LDS: ratio 1.0).
// Conflict-free strides; direct register->gmem epilogue; v6's proven
// 2-stage prefetch-before-wait pipeline. Same accumulation order as v6.
// Bank audit:
//   A frag: bank (4*gid+tig)%32 -> 32 distinct ✓
//   B frag: bank (8*tig+gid)%32 -> 32 distinct ✓
// ---------------------------------------------------------------------------
#define BM 128
#define BN 128
#define BK 32
#define LDA 36
#define LDB 136
#define A_STG (BM * LDA)                        // 4608
#define B_STG (BK * LDB)                        // 4352
#define STG_FLOATS (A_STG + B_STG)              // 8960
#define GEMM_SMEM_BYTES (2 * STG_FLOATS * 4)    // 71680

template <bool ROUND_OUT>
__global__ __launch_bounds__(128)
void gemm_bias_tf32_v7(const float* __restrict__ A, const float* __restrict__ W,
                       const float* __restrict__ bias, float* __restrict__ C,
                       int M, int N, int K) {
    extern __shared__ float sm[];
    const int tid  = threadIdx.x;
    const int warp = tid >> 5;
    const int lane = tid & 31;
    const int gid  = lane >> 2;
    const int tig  = lane & 3;
    const int wm   = warp >> 1;                 // 0..1 -> 64-row band
    const int wn   = warp & 1;                  // 0..1 -> 64-col band
    const int bm   = blockIdx.y * BM;
    const int bn   = blockIdx.x * BN;

    float acc[4][8][4];                         // [mt][nt][c-regs]
#pragma unroll
    for (int mt = 0; mt < 4; mt++)
#pragma unroll
        for (int nt = 0; nt < 8; nt++)
#pragma unroll
            for (int e = 0; e < 4; e++) acc[mt][nt][e] = 0.0f;

    auto issue = [&](int kt, int buf) {
        float* As = sm + buf * STG_FLOATS;
        float* Bs = As + A_STG;
        const float* Ag = A + (size_t)bm * K + kt * BK;
        const float* Wg = W + (size_t)(kt * BK) * N + bn;
#pragma unroll
        for (int i = 0; i < 8; i++) {           // A: 128x32 = 1024 float4
            int p   = tid + i * 128;
            int row = p >> 3;
            int col = (p & 7) * 4;
            cp_async16(&As[row * LDA + col], Ag + (size_t)row * K + col);
        }
#pragma unroll
        for (int i = 0; i < 8; i++) {           // B: 32x128 = 1024 float4
            int p   = tid + i * 128;
            int row = p >> 5;
            int col = (p & 31) * 4;
            cp_async16(&Bs[row * LDB + col], Wg + (size_t)row * N + col);
        }
    };

    const int NK = K / BK;
    issue(0, 0);
    cp_commit();

    for (int kt = 0; kt < NK; kt++) {
        if (kt + 1 < NK) {
            issue(kt + 1, (kt + 1) & 1);
            cp_commit();
            cp_wait<1>();
        } else {
            cp_wait<0>();
        }
        __syncthreads();

        const float* As = sm + (kt & 1) * STG_FLOATS;
        const float* Bs = As + A_STG;
        const int arow = (wm * 64 + gid) * LDA; // row gid of m-tile 0
        const int bcol = wn * 64 + gid;

#pragma unroll
        for (int kki = 0; kki < 4; kki++) {     // kk = kki*8
            const int kk = kki * 8;
            uint32_t af[4][4];
            uint32_t bf[8][2];
#pragma unroll
            for (int mt = 0; mt < 4; mt++) {
                const int rA = arow + mt * 16 * LDA + kk;
                af[mt][0] = __float_as_uint(As[rA + tig]);
                af[mt][1] = __float_as_uint(As[rA + 8 * LDA + tig]);
                af[mt][2] = __float_as_uint(As[rA + tig + 4]);
                af[mt][3] = __float_as_uint(As[rA + 8 * LDA + tig + 4]);
            }
#pragma unroll
            for (int nt = 0; nt < 8; nt++) {
                bf[nt][0] = __float_as_uint(Bs[(kk + tig) * LDB + bcol + nt * 8]);
                bf[nt][1] = __float_as_uint(Bs[(kk + tig + 4) * LDB + bcol + nt * 8]);
            }
#pragma unroll
            for (int nt = 0; nt < 8; nt++)
#pragma unroll
                for (int mt = 0; mt < 4; mt++)
                    mma_tf32(acc[mt][nt], af[mt], bf[nt][0], bf[nt][1]);
        }
        __syncthreads();                        // all reads done before next issue overwrites
    }

    // Direct epilogue: C layout c0=(gid,2tig) c1=(gid,2tig+1) c2/c3=row+8
#pragma unroll
    for (int mt = 0; mt < 4; mt++) {
        const int row0 = bm + wm * 64 + mt * 16 + gid;
#pragma unroll
        for (int nt = 0; nt < 8; nt++) {
            const int col = bn + wn * 64 + nt * 8 + 2 * tig;
            const float b0 = bias[col];
            const float b1 = bias[col + 1];
            float v0 = acc[mt][nt][0] + b0, v1 = acc[mt][nt][1] + b1;
            float v2 = acc[mt][nt][2] + b0, v3 = acc[mt][nt][3] + b1;
            if (ROUND_OUT) {
                v0 = roundtf(v0); v1 = roundtf(v1);
                v2 = roundtf(v2); v3 = roundtf(v3);
            }
            *reinterpret_cast<float2*>(&C[(size_t)row0 * N + col]) = make_float2(v0, v1);
            *reinterpret_cast<float2*>(&C[(size_t)(row0 + 8) * N + col]) = make_float2(v2, v3);
        }
    }
}

// ---------------------------------------------------------------------------
// Flash attention v8 (round-11 version, unchanged): register-resident FA2,
// 110.6 KB smem, 2 CTAs/SM.
// ---------------------------------------------------------------------------
#define QT 128
#define KT 64
#define LDQ 68
#define LDK 76
#define LDV 72
#define QS_FL (QT * LDQ)
#define KS_FL (KT * LDK)
#define VS_FL (KT * LDV)
#define ATTN_SMEM_FLOATS (QS_FL + 2 * KS_FL + 2 * VS_FL)
#define ATTN_SMEM_BYTES  (ATTN_SMEM_FLOATS * 4) // 110592 B

__global__ __launch_bounds__(256, 2)
void attn_fa2_tf32(const float* __restrict__ qg, const float* __restrict__ kg,
                   const float* __restrict__ vg, float* __restrict__ og) {
    extern __shared__ float smem[];
    float* Qs = smem;
    float* Kb = Qs + QS_FL;
    float* Vb = Kb + 2 * KS_FL;

    const int tid  = threadIdx.x;
    const int warp = tid >> 5;
    const int lane = tid & 31;
    const int gid  = lane >> 2;
    const int tig  = lane & 3;
    const int q0 = blockIdx.x * QT;
    const int h  = blockIdx.y;
    const int b  = blockIdx.z;
    const float scale = 0.125f;

#pragma unroll
    for (int i = 0; i < 8; i++) {
        int p   = tid + i * 256;
        int row = p >> 4;
        int col = (p & 15) * 4;
        float4 v = *reinterpret_cast<const float4*>(
            &qg[((size_t)(b * SQ + q0 + row)) * D_EMB + h * D_HEAD + col]);
        v.x *= scale; v.y *= scale; v.z *= scale; v.w *= scale;
        *reinterpret_cast<float4*>(&Qs[row * LDQ + col]) = v;
    }
    __syncthreads();

    const int r0 = warp * 16 + gid;
    uint32_t qf[8][4];
#pragma unroll
    for (int kc = 0; kc < 8; kc++) {
        qf[kc][0] = __float_as_uint(Qs[r0 * LDQ + kc * 8 + tig]);
        qf[kc][1] = __float_as_uint(Qs[(r0 + 8) * LDQ + kc * 8 + tig]);
        qf[kc][2] = __float_as_uint(Qs[r0 * LDQ + kc * 8 + tig + 4]);
        qf[kc][3] = __float_as_uint(Qs[(r0 + 8) * LDQ + kc * 8 + tig + 4]);
    }

    float o[8][4];
#pragma unroll
    for (int j = 0; j < 8; j++)
#pragma unroll
        for (int e = 0; e < 4; e++) o[j][e] = 0.0f;
    float m0 = -1e30f, m1 = -1e30f, l0 = 0.0f, l1 = 0.0f;

    auto issue_kv = [&](int kt, int buf) {
        const int k0 = kt * KT;
        float* Ks = Kb + buf * KS_FL;
        float* Vs = Vb + buf * VS_FL;
#pragma unroll
        for (int i = 0; i < 4; i++) {
            int p   = tid + i * 256;
            int row = p >> 4;
            int col = (p & 15) * 4;
            size_t g = ((size_t)(b * SK + k0 + row)) * D_EMB + h * D_HEAD + col;
            cp_async16(&Ks[row * LDK + col], &kg[g]);
            cp_async16(&Vs[row * LDV + col], &vg[g]);
        }
    };

    issue_kv(0, 0);
    cp_commit();

    const int NKT = SK / KT;
    for (int kt = 0; kt < NKT; kt++) {
        if (kt + 1 < NKT) {
            issue_kv(kt + 1, (kt + 1) & 1);
            cp_commit();
            cp_wait<1>();
        } else {
            cp_wait<0>();
        }
        __syncthreads();

        const float* Ks = Kb + (kt & 1) * KS_FL;
        const float* Vs = Vb + (kt & 1) * VS_FL;

        float s[8][4];
#pragma unroll
        for (int j = 0; j < 8; j++)
#pragma unroll
            for (int e = 0; e < 4; e++) s[j][e] = 0.0f;

#pragma unroll
        for (int kc = 0; kc < 8; kc++) {
#pragma unroll
            for (int j = 0; j < 8; j++) {
                uint32_t b0 = __float_as_uint(Ks[(j * 8 + gid) * LDK + kc * 8 + tig]);
                uint32_t b1 = __float_as_uint(Ks[(j * 8 + gid) * LDK + kc * 8 + tig + 4]);
                mma_tf32(s[j], qf[kc], b0, b1);
            }
        }

        float mx0 = -1e30f, mx1 = -1e30f;
#pragma unroll
        for (int j = 0; j < 8; j++) {
            mx0 = fmaxf(mx0, fmaxf(s[j][0], s[j][1]));
            mx1 = fmaxf(mx1, fmaxf(s[j][2], s[j][3]));
        }
        mx0 = fmaxf(mx0, __shfl_xor_sync(0xffffffffu, mx0, 1));
        mx0 = fmaxf(mx0, __shfl_xor_sync(0xffffffffu, mx0, 2));
        mx1 = fmaxf(mx1, __shfl_xor_sync(0xffffffffu, mx1, 1));
        mx1 = fmaxf(mx1, __shfl_xor_sync(0xffffffffu, mx1, 2));

        const float mn0 = fmaxf(m0, mx0);
        const float mn1 = fmaxf(m1, mx1);
        float sum0 = 0.0f, sum1 = 0.0f;
#pragma unroll
        for (int j = 0; j < 8; j++) {
            s[j][0] = __expf(s[j][0] - mn0);
            s[j][1] = __expf(s[j][1] - mn0);
            s[j][2] = __expf(s[j][2] - mn1);
            s[j][3] = __expf(s[j][3] - mn1);
            sum0 += s[j][0] + s[j][1];
            sum1 += s[j][2] + s[j][3];
        }
        sum0 += __shfl_xor_sync(0xffffffffu, sum0, 1);
        sum0 += __shfl_xor_sync(0xffffffffu, sum0, 2);
        sum1 += __shfl_xor_sync(0xffffffffu, sum1, 1);
        sum1 += __shfl_xor_sync(0xffffffffu, sum1, 2);

        const float al0 = __expf(m0 - mn0);
        const float al1 = __expf(m1 - mn1);
        l0 = l0 * al0 + sum0;
        l1 = l1 * al1 + sum1;
        m0 = mn0; m1 = mn1;

#pragma unroll
        for (int j = 0; j < 8; j++) {
            o[j][0] *= al0; o[j][1] *= al0;
            o[j][2] *= al1; o[j][3] *= al1;
        }

        uint32_t pa[8][4];
        const int srcA = (lane & ~3) | (tig >> 1);
        const int srcB = (lane & ~3) | (2 + (tig >> 1));
        const bool oddc = (tig & 1);
#pragma unroll
        for (int j = 0; j < 8; j++) {
            float x0 = __shfl_sync(0xffffffffu, s[j][0], srcA);
            float x1 = __shfl_sync(0xffffffffu, s[j][1], srcA);
            float y0 = __shfl_sync(0xffffffffu, s[j][0], srcB);
            float y1 = __shfl_sync(0xffffffffu, s[j][1], srcB);
            float z0 = __shfl_sync(0xffffffffu, s[j][2], srcA);
            float z1 = __shfl_sync(0xffffffffu, s[j][3], srcA);
            float w0 = __shfl_sync(0xffffffffu, s[j][2], srcB);
            float w1 = __shfl_sync(0xffffffffu, s[j][3], srcB);
            pa[j][0] = f2tf(oddc ? x1 : x0);
            pa[j][1] = f2tf(oddc ? z1 : z0);
            pa[j][2] = f2tf(oddc ? y1 : y0);
            pa[j][3] = f2tf(oddc ? w1 : w0);
        }

#pragma unroll
        for (int kc = 0; kc < 8; kc++) {
#pragma unroll
            for (int j = 0; j < 8; j++) {
                uint32_t b0 = __float_as_uint(Vs[(kc * 8 + tig) * LDV + j * 8 + gid]);
                uint32_t b1 = __float_as_uint(Vs[(kc * 8 + tig + 4) * LDV + j * 8 + gid]);
                mma_tf32(o[j], pa[kc], b0, b1);
            }
        }
        __syncthreads();
    }

    const float inv0 = 1.0f / l0;
    const float inv1 = 1.0f / l1;
    const size_t rowbase0 = ((size_t)(b * SQ + q0 + r0)) * D_EMB + h * D_HEAD;
    const size_t rowbase1 = rowbase0 + 8 * D_EMB;
#pragma unroll
    for (int j = 0; j < 8; j++) {
        int col = j * 8 + 2 * tig;
        *reinterpret_cast<float2*>(&og[rowbase0 + col]) =
            make_float2(roundtf(o[j][0] * inv0), roundtf(o[j][1] * inv0));
        *reinterpret_cast<float2*>(&og[rowbase1 + col]) =
            make_float2(roundtf(o[j][2] * inv1), roundtf(o[j][3] * inv1));
    }
}

// ---------------------------------------------------------------------------
// Launcher
// ---------------------------------------------------------------------------
extern "C" void kernel_launch(void* const* d_in, const int* in_sizes, int n_in,
                              void* d_out, int out_size) {
    const float* x  = (const float*)d_in[0];
    const float* y  = (const float*)d_in[1];
    const float* Wq = (const float*)d_in[2];
    const float* bq = (const float*)d_in[3];
    const float* Wk = (const float*)d_in[4];
    const float* bk = (const float*)d_in[5];
    const float* Wv = (const float*)d_in[6];
    const float* bv = (const float*)d_in[7];
    const float* Wo = (const float*)d_in[8];
    const float* bo = (const float*)d_in[9];
    float* out = (float*)d_out;

    float *gq, *gk, *gv, *ga, *xr, *yr, *wqr, *wkr, *wvr, *wor;
    cudaGetSymbolAddress((void**)&gq, g_q);
    cudaGetSymbolAddress((void**)&gk, g_k);
    cudaGetSymbolAddress((void**)&gv, g_v);
    cudaGetSymbolAddress((void**)&ga, g_attn);
    cudaGetSymbolAddress((void**)&xr, g_xr);
    cudaGetSymbolAddress((void**)&yr, g_yr);
    cudaGetSymbolAddress((void**)&wqr, g_wq);
    cudaGetSymbolAddress((void**)&wkr, g_wk);
    cudaGetSymbolAddress((void**)&wvr, g_wv);
    cudaGetSymbolAddress((void**)&wor, g_wo);

    cudaFuncSetAttribute(gemm_bias_tf32_v7<true>,
                         cudaFuncAttributeMaxDynamicSharedMemorySize, GEMM_SMEM_BYTES);
    cudaFuncSetAttribute(gemm_bias_tf32_v7<false>,
                         cudaFuncAttributeMaxDynamicSharedMemorySize, GEMM_SMEM_BYTES);
    cudaFuncSetAttribute(attn_fa2_tf32,
                         cudaFuncAttributeMaxDynamicSharedMemorySize, ATTN_SMEM_BYTES);

    // Pre-round inputs + weights to tf32
    preround_all<<<2048, 256>>>((const float4*)x, (const float4*)y,
                                (const float4*)Wq, (const float4*)Wk,
                                (const float4*)Wv, (const float4*)Wo,
                                (float4*)xr, (float4*)yr, (float4*)wqr,
                                (float4*)wkr, (float4*)wvr, (float4*)wor);

    // Projections (outputs tf32-rounded)
    gemm_bias_tf32_v7<true><<<dim3(D_EMB / BN, (BATCH * SQ) / BM), 128, GEMM_SMEM_BYTES>>>(
        xr, wqr, bq, gq, BATCH * SQ, D_EMB, D_EMB);
    gemm_bias_tf32_v7<true><<<dim3(D_EMB / BN, (BATCH * SK) / BM), 128, GEMM_SMEM_BYTES>>>(
        yr, wkr, bk, gk, BATCH * SK, D_EMB, D_CRUZ);
    gemm_bias_tf32_v7<true><<<dim3(D_EMB / BN, (BATCH * SK) / BM), 128, GEMM_SMEM_BYTES>>>(
        yr, wvr, bv, gv, BATCH * SK, D_EMB, D_CRUZ);

    // Attention (register-resident FA2)
    attn_fa2_tf32<<<dim3(SQ / QT, N_HEADS, BATCH), 256, ATTN_SMEM_BYTES>>>(gq, gk, gv, ga);

    // Output projection (full-precision fp32 output)
    gemm_bias_tf32_v7<false><<<dim3(D_EMB / BN, (BATCH * SQ) / BM), 128, GEMM_SMEM_BYTES>>>(
        ga, wor, bo, out, BATCH * SQ, D_EMB, D_EMB);
}

// round 17
// speedup vs baseline: 1.7534x; 1.0314x over previous
#include <cuda_runtime.h>
#include <cuda_bf16.h>
#include <mma.h>
#include <cstdint>

// Problem constants
#define BATCH   4
#define SQ      4096
#define SK      1024
#define D_EMB   1024
#define D_CRUZ  768
#define N_HEADS 16
#define D_HEAD  64

// Scratch (static device allocations — allowed)
__device__ float g_q[BATCH * SQ * D_EMB];     // 64 MB
__device__ float g_k[BATCH * SK * D_EMB];     // 16 MB
__device__ float g_v[BATCH * SK * D_EMB];     // 16 MB
__device__ float g_attn[BATCH * SQ * D_EMB];  // 64 MB
// tf32-pre-rounded inputs/weights
__device__ float g_xr[BATCH * SQ * D_EMB];    // 64 MB
__device__ float g_yr[BATCH * SK * D_CRUZ];   // 12 MB
__device__ float g_wq[D_EMB * D_EMB];         // 4 MB
__device__ float g_wk[D_CRUZ * D_EMB];        // 3 MB
__device__ float g_wv[D_CRUZ * D_EMB];        // 3 MB
__device__ float g_wo[D_EMB * D_EMB];         // 4 MB

// ---------------------------------------------------------------------------
// helpers
// ---------------------------------------------------------------------------
__device__ __forceinline__ void cp_async16(float* dst_smem, const float* src) {
    unsigned int d = (unsigned int)__cvta_generic_to_shared(dst_smem);
    asm volatile("cp.async.ca.shared.global [%0], [%1], 16;\n" :: "r"(d), "l"(src));
}
__device__ __forceinline__ void cp_commit() {
    asm volatile("cp.async.commit_group;\n");
}
template <int N>
__device__ __forceinline__ void cp_wait() {
    asm volatile("cp.async.wait_group %0;\n" :: "n"(N));
}

__device__ __forceinline__ uint32_t f2tf(float f) {
    uint32_t u;
    asm("cvt.rna.tf32.f32 %0, %1;" : "=r"(u) : "f"(f));
    return u;
}
__device__ __forceinline__ float roundtf(float f) {
    return __uint_as_float(f2tf(f));
}

// mma.m16n8k8 tf32 (verified layouts; gid=lane>>2, tig=lane&3):
//   A: a0=(gid,tig) a1=(gid+8,tig) a2=(gid,tig+4) a3=(gid+8,tig+4)
//   B: b0=(k=tig,n=gid) b1=(k=tig+4,n=gid)
//   C: c0=(gid,2tig) c1=(gid,2tig+1) c2=(gid+8,2tig) c3=(gid+8,2tig+1)
__device__ __forceinline__ void mma_tf32(float* d, const uint32_t* a,
                                         uint32_t b0, uint32_t b1) {
    asm volatile(
        "mma.sync.aligned.m16n8k8.row.col.f32.tf32.tf32.f32 "
        "{%0,%1,%2,%3}, {%4,%5,%6,%7}, {%8,%9}, {%0,%1,%2,%3};"
        : "+f"(d[0]), "+f"(d[1]), "+f"(d[2]), "+f"(d[3])
        : "r"(a[0]), "r"(a[1]), "r"(a[2]), "r"(a[3]), "r"(b0), "r"(b1));
}

// ---------------------------------------------------------------------------
// Pre-round: convert x, y, and the four weight matrices to tf32-rounded fp32.
// ---------------------------------------------------------------------------
#define SEG_X  4194304
#define SEG_Y  (SEG_X + 786432)
#define SEG_WQ (SEG_Y + 262144)
#define SEG_WK (SEG_WQ + 196608)
#define SEG_WV (SEG_WK + 196608)
#define SEG_WO (SEG_WV + 262144)

__global__ __launch_bounds__(256)
void preround_all(const float4* __restrict__ x, const float4* __restrict__ y,
                  const float4* __restrict__ wq, const float4* __restrict__ wk,
                  const float4* __restrict__ wv, const float4* __restrict__ wo,
                  float4* __restrict__ xr, float4* __restrict__ yr,
                  float4* __restrict__ wqr, float4* __restrict__ wkr,
                  float4* __restrict__ wvr, float4* __restrict__ wor) {
    for (long i = (long)blockIdx.x * blockDim.x + threadIdx.x; i < SEG_WO;
         i += (long)gridDim.x * blockDim.x) {
        const float4* src; float4* dst; long o;
        if (i < SEG_X)       { src = x;  dst = xr;  o = i; }
        else if (i < SEG_Y)  { src = y;  dst = yr;  o = i - SEG_X; }
        else if (i < SEG_WQ) { src = wq; dst = wqr; o = i - SEG_Y; }
        else if (i < SEG_WK) { src = wk; dst = wkr; o = i - SEG_WQ; }
        else if (i < SEG_WV) { src = wv; dst = wvr; o = i - SEG_WK; }
        else                 { src = wo; dst = wor; o = i - SEG_WV; }
        float4 v = src[o];
        v.x = roundtf(v.x); v.y = roundtf(v.y);
        v.z = roundtf(v.z); v.w = roundtf(v.w);
        dst[o] = v;
    }
}

// ---------------------------------------------------------------------------
// GEMM core (v7 layout): raw mma.sync, 128x128x32 tiles, 4 warps, warp tile
// 64x64, conflict-free strides, direct register epilogue.
// ---------------------------------------------------------------------------
#define BM 128
#define BN 128
#define BK 32
#define LDA 36
#define LDB 136
#define A_STG (BM * LDA)
#define B_STG (BK * LDB)
#define STG_FLOATS (A_STG + B_STG)
#define GEMM_SMEM_BYTES (2 * STG_FLOATS * 4)    // 71680

template <bool ROUND_OUT>
__device__ __forceinline__ void gemm_core(
    const float* __restrict__ A, const float* __restrict__ W,
    const float* __restrict__ bias, float* __restrict__ C,
    int bm, int bn, int N, int K, float* sm) {
    const int tid  = threadIdx.x;
    const int warp = tid >> 5;
    const int lane = tid & 31;
    const int gid  = lane >> 2;
    const int tig  = lane & 3;
    const int wm   = warp >> 1;
    const int wn   = warp & 1;

    float acc[4][8][4];
#pragma unroll
    for (int mt = 0; mt < 4; mt++)
#pragma unroll
        for (int nt = 0; nt < 8; nt++)
#pragma unroll
            for (int e = 0; e < 4; e++) acc[mt][nt][e] = 0.0f;

    auto issue = [&](int kt, int buf) {
        float* As = sm + buf * STG_FLOATS;
        float* Bs = As + A_STG;
        const float* Ag = A + (size_t)bm * K + kt * BK;
        const float* Wg = W + (size_t)(kt * BK) * N + bn;
#pragma unroll
        for (int i = 0; i < 8; i++) {
            int p   = tid + i * 128;
            int row = p >> 3;
            int col = (p & 7) * 4;
            cp_async16(&As[row * LDA + col], Ag + (size_t)row * K + col);
        }
#pragma unroll
        for (int i = 0; i < 8; i++) {
            int p   = tid + i * 128;
            int row = p >> 5;
            int col = (p & 31) * 4;
            cp_async16(&Bs[row * LDB + col], Wg + (size_t)row * N + col);
        }
    };

    const int NK = K / BK;
    issue(0, 0);
    cp_commit();

    for (int kt = 0; kt < NK; kt++) {
        if (kt + 1 < NK) {
            issue(kt + 1, (kt + 1) & 1);
            cp_commit();
            cp_wait<1>();
        } else {
            cp_wait<0>();
        }
        __syncthreads();

        const float* As = sm + (kt & 1) * STG_FLOATS;
        const float* Bs = As + A_STG;
        const int arow = (wm * 64 + gid) * LDA;
        const int bcol = wn * 64 + gid;

#pragma unroll
        for (int kki = 0; kki < 4; kki++) {
            const int kk = kki * 8;
            uint32_t af[4][4];
            uint32_t bf[8][2];
#pragma unroll
            for (int mt = 0; mt < 4; mt++) {
                const int rA = arow + mt * 16 * LDA + kk;
                af[mt][0] = __float_as_uint(As[rA + tig]);
                af[mt][1] = __float_as_uint(As[rA + 8 * LDA + tig]);
                af[mt][2] = __float_as_uint(As[rA + tig + 4]);
                af[mt][3] = __float_as_uint(As[rA + 8 * LDA + tig + 4]);
            }
#pragma unroll
            for (int nt = 0; nt < 8; nt++) {
                bf[nt][0] = __float_as_uint(Bs[(kk + tig) * LDB + bcol + nt * 8]);
                bf[nt][1] = __float_as_uint(Bs[(kk + tig + 4) * LDB + bcol + nt * 8]);
            }
#pragma unroll
            for (int nt = 0; nt < 8; nt++)
#pragma unroll
                for (int mt = 0; mt < 4; mt++)
                    mma_tf32(acc[mt][nt], af[mt], bf[nt][0], bf[nt][1]);
        }
        __syncthreads();
    }

#pragma unroll
    for (int mt = 0; mt < 4; mt++) {
        const int row0 = bm + wm * 64 + mt * 16 + gid;
#pragma unroll
        for (int nt = 0; nt < 8; nt++) {
            const int col = bn + wn * 64 + nt * 8 + 2 * tig;
            const float b0 = bias[col];
            const float b1 = bias[col + 1];
            float v0 = acc[mt][nt][0] + b0, v1 = acc[mt][nt][1] + b1;
            float v2 = acc[mt][nt][2] + b0, v3 = acc[mt][nt][3] + b1;
            if (ROUND_OUT) {
                v0 = roundtf(v0); v1 = roundtf(v1);
                v2 = roundtf(v2); v3 = roundtf(v3);
            }
            *reinterpret_cast<float2*>(&C[(size_t)row0 * N + col]) = make_float2(v0, v1);
            *reinterpret_cast<float2*>(&C[(size_t)(row0 + 8) * N + col]) = make_float2(v2, v3);
        }
    }
}

// Fused Q/K/V projection: grid.y segments [0,128)=Q, [128,160)=K, [160,192)=V
__global__ __launch_bounds__(128)
void gemm_qkv_fused(const float* __restrict__ xr, const float* __restrict__ yr,
                    const float* __restrict__ wq, const float* __restrict__ wk,
                    const float* __restrict__ wv,
                    const float* __restrict__ bq, const float* __restrict__ bk,
                    const float* __restrict__ bv,
                    float* __restrict__ q, float* __restrict__ k,
                    float* __restrict__ v) {
    extern __shared__ float sm[];
    const int by = blockIdx.y;
    const int bn = blockIdx.x * BN;
    if (by < 128) {
        gemm_core<true>(xr, wq, bq, q, by * BM, bn, D_EMB, D_EMB, sm);
    } else if (by < 160) {
        gemm_core<true>(yr, wk, bk, k, (by - 128) * BM, bn, D_EMB, D_CRUZ, sm);
    } else {
        gemm_core<true>(yr, wv, bv, v, (by - 160) * BM, bn, D_EMB, D_CRUZ, sm);
    }
}

// Standalone O-projection (fp32 out)
__global__ __launch_bounds__(128)
void gemm_o(const float* __restrict__ A, const float* __restrict__ W,
            const float* __restrict__ bias, float* __restrict__ C,
            int M, int N, int K) {
    extern __shared__ float sm[];
    gemm_core<false>(A, W, bias, C, blockIdx.y * BM, blockIdx.x * BN, N, K, sm);
}

// ---------------------------------------------------------------------------
// Flash attention v9: KT=128 (8 softmax phases instead of 16), 128-row Q tile,
// 256 threads, register-resident. smem ~186 KB -> 1 CTA/SM.
// ---------------------------------------------------------------------------
#define QT 128
#define KT 128
#define LDQ 68
#define LDK 76
#define LDV 72
#define QS_FL (QT * LDQ)                        // 8704
#define KS_FL (KT * LDK)                        // 9728
#define VS_FL (KT * LDV)                        // 9216
#define ATTN_SMEM_FLOATS (QS_FL + 2 * KS_FL + 2 * VS_FL)
#define ATTN_SMEM_BYTES  (ATTN_SMEM_FLOATS * 4) // 186368 B

__global__ __launch_bounds__(256, 1)
void attn_fa2_tf32(const float* __restrict__ qg, const float* __restrict__ kg,
                   const float* __restrict__ vg, float* __restrict__ og) {
    extern __shared__ float smem[];
    float* Qs = smem;
    float* Kb = Qs + QS_FL;
    float* Vb = Kb + 2 * KS_FL;

    const int tid  = threadIdx.x;
    const int warp = tid >> 5;
    const int lane = tid & 31;
    const int gid  = lane >> 2;
    const int tig  = lane & 3;
    const int q0 = blockIdx.x * QT;
    const int h  = blockIdx.y;
    const int b  = blockIdx.z;
    const float scale = 0.125f;

#pragma unroll
    for (int i = 0; i < 8; i++) {
        int p   = tid + i * 256;
        int row = p >> 4;
        int col = (p & 15) * 4;
        float4 v = *reinterpret_cast<const float4*>(
            &qg[((size_t)(b * SQ + q0 + row)) * D_EMB + h * D_HEAD + col]);
        v.x *= scale; v.y *= scale; v.z *= scale; v.w *= scale;
        *reinterpret_cast<float4*>(&Qs[row * LDQ + col]) = v;
    }
    __syncthreads();

    const int r0 = warp * 16 + gid;
    uint32_t qf[8][4];
#pragma unroll
    for (int kc = 0; kc < 8; kc++) {
        qf[kc][0] = __float_as_uint(Qs[r0 * LDQ + kc * 8 + tig]);
        qf[kc][1] = __float_as_uint(Qs[(r0 + 8) * LDQ + kc * 8 + tig]);
        qf[kc][2] = __float_as_uint(Qs[r0 * LDQ + kc * 8 + tig + 4]);
        qf[kc][3] = __float_as_uint(Qs[(r0 + 8) * LDQ + kc * 8 + tig + 4]);
    }

    float o[8][4];
#pragma unroll
    for (int j = 0; j < 8; j++)
#pragma unroll
        for (int e = 0; e < 4; e++) o[j][e] = 0.0f;
    float m0 = -1e30f, m1 = -1e30f, l0 = 0.0f, l1 = 0.0f;

    auto issue_kv = [&](int kt, int buf) {
        const int k0 = kt * KT;
        float* Ks = Kb + buf * KS_FL;
        float* Vs = Vb + buf * VS_FL;
#pragma unroll
        for (int i = 0; i < 8; i++) {           // 128x64 = 2048 float4 per tensor
            int p   = tid + i * 256;
            int row = p >> 4;
            int col = (p & 15) * 4;
            size_t g = ((size_t)(b * SK + k0 + row)) * D_EMB + h * D_HEAD + col;
            cp_async16(&Ks[row * LDK + col], &kg[g]);
            cp_async16(&Vs[row * LDV + col], &vg[g]);
        }
    };

    issue_kv(0, 0);
    cp_commit();

    const int NKT = SK / KT;                    // 8
    for (int kt = 0; kt < NKT; kt++) {
        if (kt + 1 < NKT) {
            issue_kv(kt + 1, (kt + 1) & 1);
            cp_commit();
            cp_wait<1>();
        } else {
            cp_wait<0>();
        }
        __syncthreads();

        const float* Ks = Kb + (kt & 1) * KS_FL;
        const float* Vs = Vb + (kt & 1) * VS_FL;

        // ---- S = Q @ K^T over 128 keys: s[j] = keys j*8..j*8+7, j=0..15 ----
        float s[16][4];
#pragma unroll
        for (int j = 0; j < 16; j++)
#pragma unroll
            for (int e = 0; e < 4; e++) s[j][e] = 0.0f;

#pragma unroll
        for (int kc = 0; kc < 8; kc++) {
#pragma unroll
            for (int j = 0; j < 16; j++) {
                uint32_t b0 = __float_as_uint(Ks[(j * 8 + gid) * LDK + kc * 8 + tig]);
                uint32_t b1 = __float_as_uint(Ks[(j * 8 + gid) * LDK + kc * 8 + tig + 4]);
                mma_tf32(s[j], qf[kc], b0, b1);
            }
        }

        // ---- online softmax (one phase per 128 keys) ----
        float mx0 = -1e30f, mx1 = -1e30f;
#pragma unroll
        for (int j = 0; j < 16; j++) {
            mx0 = fmaxf(mx0, fmaxf(s[j][0], s[j][1]));
            mx1 = fmaxf(mx1, fmaxf(s[j][2], s[j][3]));
        }
        mx0 = fmaxf(mx0, __shfl_xor_sync(0xffffffffu, mx0, 1));
        mx0 = fmaxf(mx0, __shfl_xor_sync(0xffffffffu, mx0, 2));
        mx1 = fmaxf(mx1, __shfl_xor_sync(0xffffffffu, mx1, 1));
        mx1 = fmaxf(mx1, __shfl_xor_sync(0xffffffffu, mx1, 2));

        const float mn0 = fmaxf(m0, mx0);
        const float mn1 = fmaxf(m1, mx1);
        float sum0 = 0.0f, sum1 = 0.0f;
#pragma unroll
        for (int j = 0; j < 16; j++) {
            s[j][0] = __expf(s[j][0] - mn0);
            s[j][1] = __expf(s[j][1] - mn0);
            s[j][2] = __expf(s[j][2] - mn1);
            s[j][3] = __expf(s[j][3] - mn1);
            sum0 += s[j][0] + s[j][1];
            sum1 += s[j][2] + s[j][3];
        }
        sum0 += __shfl_xor_sync(0xffffffffu, sum0, 1);
        sum0 += __shfl_xor_sync(0xffffffffu, sum0, 2);
        sum1 += __shfl_xor_sync(0xffffffffu, sum1, 1);
        sum1 += __shfl_xor_sync(0xffffffffu, sum1, 2);

        const float al0 = __expf(m0 - mn0);
        const float al1 = __expf(m1 - mn1);
        l0 = l0 * al0 + sum0;
        l1 = l1 * al1 + sum1;
        m0 = mn0; m1 = mn1;

#pragma unroll
        for (int j = 0; j < 8; j++) {
            o[j][0] *= al0; o[j][1] *= al0;
            o[j][2] *= al1; o[j][3] *= al1;
        }

        // ---- permute P: C layout -> A layout (shuffles), cvt once ----
        uint32_t pa[16][4];
        const int srcA = (lane & ~3) | (tig >> 1);
        const int srcB = (lane & ~3) | (2 + (tig >> 1));
        const bool oddc = (tig & 1);
#pragma unroll
        for (int j = 0; j < 16; j++) {
            float x0 = __shfl_sync(0xffffffffu, s[j][0], srcA);
            float x1 = __shfl_sync(0xffffffffu, s[j][1], srcA);
            float y0 = __shfl_sync(0xffffffffu, s[j][0], srcB);
            float y1 = __shfl_sync(0xffffffffu, s[j][1], srcB);
            float z0 = __shfl_sync(0xffffffffu, s[j][2], srcA);
            float z1 = __shfl_sync(0xffffffffu, s[j][3], srcA);
            float w0 = __shfl_sync(0xffffffffu, s[j][2], srcB);
            float w1 = __shfl_sync(0xffffffffu, s[j][3], srcB);
            pa[j][0] = f2tf(oddc ? x1 : x0);
            pa[j][1] = f2tf(oddc ? z1 : z0);
            pa[j][2] = f2tf(oddc ? y1 : y0);
            pa[j][3] = f2tf(oddc ? w1 : w0);
        }

        // ---- O += P @ V over 128 keys: kc = 0..15 key chunks ----
#pragma unroll
        for (int kc = 0; kc < 16; kc++) {
#pragma unroll
            for (int j = 0; j < 8; j++) {
                uint32_t b0 = __float_as_uint(Vs[(kc * 8 + tig) * LDV + j * 8 + gid]);
                uint32_t b1 = __float_as_uint(Vs[(kc * 8 + tig + 4) * LDV + j * 8 + gid]);
                mma_tf32(o[j], pa[kc], b0, b1);
            }
        }
        __syncthreads();
    }

    const float inv0 = 1.0f / l0;
    const float inv1 = 1.0f / l1;
    const size_t rowbase0 = ((size_t)(b * SQ + q0 + r0)) * D_EMB + h * D_HEAD;
    const size_t rowbase1 = rowbase0 + 8 * D_EMB;
#pragma unroll
    for (int j = 0; j < 8; j++) {
        int col = j * 8 + 2 * tig;
        *reinterpret_cast<float2*>(&og[rowbase0 + col]) =
            make_float2(roundtf(o[j][0] * inv0), roundtf(o[j][1] * inv0));
        *reinterpret_cast<float2*>(&og[rowbase1 + col]) =
            make_float2(roundtf(o[j][2] * inv1), roundtf(o[j][3] * inv1));
    }
}

// ---------------------------------------------------------------------------
// Launcher
// ---------------------------------------------------------------------------
extern "C" void kernel_launch(void* const* d_in, const int* in_sizes, int n_in,
                              void* d_out, int out_size) {
    const float* x  = (const float*)d_in[0];
    const float* y  = (const float*)d_in[1];
    const float* Wq = (const float*)d_in[2];
    const float* bq = (const float*)d_in[3];
    const float* Wk = (const float*)d_in[4];
    const float* bk = (const float*)d_in[5];
    const float* Wv = (const float*)d_in[6];
    const float* bv = (const float*)d_in[7];
    const float* Wo = (const float*)d_in[8];
    const float* bo = (const float*)d_in[9];
    float* out = (float*)d_out;

    float *gq, *gk, *gv, *ga, *xr, *yr, *wqr, *wkr, *wvr, *wor;
    cudaGetSymbolAddress((void**)&gq, g_q);
    cudaGetSymbolAddress((void**)&gk, g_k);
    cudaGetSymbolAddress((void**)&gv, g_v);
    cudaGetSymbolAddress((void**)&ga, g_attn);
    cudaGetSymbolAddress((void**)&xr, g_xr);
    cudaGetSymbolAddress((void**)&yr, g_yr);
    cudaGetSymbolAddress((void**)&wqr, g_wq);
    cudaGetSymbolAddress((void**)&wkr, g_wk);
    cudaGetSymbolAddress((void**)&wvr, g_wv);
    cudaGetSymbolAddress((void**)&wor, g_wo);

    cudaFuncSetAttribute(gemm_qkv_fused,
                         cudaFuncAttributeMaxDynamicSharedMemorySize, GEMM_SMEM_BYTES);
    cudaFuncSetAttribute(gemm_o,
                         cudaFuncAttributeMaxDynamicSharedMemorySize, GEMM_SMEM_BYTES);
    cudaFuncSetAttribute(attn_fa2_tf32,
                         cudaFuncAttributeMaxDynamicSharedMemorySize, ATTN_SMEM_BYTES);

    // Pre-round inputs + weights to tf32
    preround_all<<<2048, 256>>>((const float4*)x, (const float4*)y,
                                (const float4*)Wq, (const float4*)Wk,
                                (const float4*)Wv, (const float4*)Wo,
                                (float4*)xr, (float4*)yr, (float4*)wqr,
                                (float4*)wkr, (float4*)wvr, (float4*)wor);

    // Fused Q/K/V projections (one launch; K/V ride inside Q's waves)
    gemm_qkv_fused<<<dim3(D_EMB / BN, 192), 128, GEMM_SMEM_BYTES>>>(
        xr, yr, wqr, wkr, wvr, bq, bk, bv, gq, gk, gv);

    // Attention (register-resident FA2, KT=128)
    attn_fa2_tf32<<<dim3(SQ / QT, N_HEADS, BATCH), 256, ATTN_SMEM_BYTES>>>(gq, gk, gv, ga);

    // Output projection (full-precision fp32 output)
    gemm_o<<<dim3(D_EMB / BN, (BATCH * SQ) / BM), 128, GEMM_SMEM_BYTES>>>(
        ga, wor, bo, out, BATCH * SQ, D_EMB, D_EMB);
}